// round 1
// baseline (speedup 1.0000x reference)
#include <cuda_runtime.h>
#include <cuda_bf16.h>

#define D_MODEL 1024
#define HEADS   16
#define DH      64
#define BATCH   4
#define SEQ     2048
#define NTOK    (BATCH * SEQ)   // 8192

// Scratch (device globals; no runtime allocation allowed)
__device__ float g_qkv[(size_t)NTOK * 3 * D_MODEL]; // 96 MB: [8192, 3072]
__device__ float g_ctx[(size_t)NTOK * D_MODEL];     // 32 MB: [8192, 1024]

// ---------------------------------------------------------------------------
// SGEMM with bias: C[M,N] = A[M,K] @ B[K,N] + bias[N]   (row-major, fp32)
// Tile 128x128x16, 256 threads, 8x8 per thread.
// ---------------------------------------------------------------------------
#define GBM 128
#define GBN 128
#define GBK 16
#define GTM 8
#define GTN 8
#define APAD 4

__global__ __launch_bounds__(256) void sgemm_bias_kernel(
    int M, int N, int K,
    const float* __restrict__ A,
    const float* __restrict__ B,
    const float* __restrict__ bias,
    float* __restrict__ C)
{
    __shared__ float As[GBK][GBM + APAD];  // transposed A tile
    __shared__ float Bs[GBK][GBN];

    const int tid = threadIdx.x;
    const int block_row = blockIdx.y;
    const int block_col = blockIdx.x;

    const float* Ablk = A + (size_t)block_row * GBM * K;
    const float* Bblk = B + (size_t)block_col * GBN;
    float* Cblk = C + (size_t)block_row * GBM * N + (size_t)block_col * GBN;

    // A tile loads: 128 rows x 16 cols -> 512 float4, 2 per thread
    const int aRow = tid >> 2;          // 0..63
    const int aCol = (tid & 3) * 4;     // 0,4,8,12
    // B tile loads: 16 rows x 128 cols -> 512 float4, 2 per thread
    const int bRow = tid >> 5;          // 0..7
    const int bCol = (tid & 31) * 4;    // 0..124

    const int tRow = (tid >> 4) * GTM;  // 0..120
    const int tCol = (tid & 15) * GTN;  // 0..120

    float acc[GTM][GTN] = {};
    float regM[GTM], regN[GTN];

    for (int k0 = 0; k0 < K; k0 += GBK) {
#pragma unroll
        for (int i = 0; i < 2; i++) {
            int r = aRow + i * 64;
            float4 v = *(const float4*)(Ablk + (size_t)r * K + k0 + aCol);
            As[aCol + 0][r] = v.x;
            As[aCol + 1][r] = v.y;
            As[aCol + 2][r] = v.z;
            As[aCol + 3][r] = v.w;
        }
#pragma unroll
        for (int i = 0; i < 2; i++) {
            int r = bRow + i * 8;
            *(float4*)(&Bs[r][bCol]) = *(const float4*)(Bblk + (size_t)(k0 + r) * N + bCol);
        }
        __syncthreads();

#pragma unroll
        for (int kk = 0; kk < GBK; kk++) {
#pragma unroll
            for (int i = 0; i < GTM; i += 4) {
                float4 v = *(const float4*)(&As[kk][tRow + i]);
                regM[i + 0] = v.x; regM[i + 1] = v.y; regM[i + 2] = v.z; regM[i + 3] = v.w;
            }
#pragma unroll
            for (int j = 0; j < GTN; j += 4) {
                float4 v = *(const float4*)(&Bs[kk][tCol + j]);
                regN[j + 0] = v.x; regN[j + 1] = v.y; regN[j + 2] = v.z; regN[j + 3] = v.w;
            }
#pragma unroll
            for (int i = 0; i < GTM; i++)
#pragma unroll
                for (int j = 0; j < GTN; j++)
                    acc[i][j] += regM[i] * regN[j];
        }
        __syncthreads();
    }

    // Epilogue: add bias, store
#pragma unroll
    for (int i = 0; i < GTM; i++) {
#pragma unroll
        for (int j = 0; j < GTN; j += 4) {
            float4 bv = *(const float4*)(bias + (size_t)block_col * GBN + tCol + j);
            float4 v;
            v.x = acc[i][j + 0] + bv.x;
            v.y = acc[i][j + 1] + bv.y;
            v.z = acc[i][j + 2] + bv.z;
            v.w = acc[i][j + 3] + bv.w;
            *(float4*)(Cblk + (size_t)(tRow + i) * N + tCol + j) = v;
        }
    }
}

// ---------------------------------------------------------------------------
// Flash attention (fp32): per block = one (b,h) pair, 64 query rows.
// qkv layout: [NTOK, 3072]; Q cols [h*64, h*64+64), K at +1024, V at +2048.
// ctx layout: [NTOK, 1024], col = h*64 + d.
// ---------------------------------------------------------------------------
#define FBQ  64
#define FBKV 64
#define FPAD 4
#define FLD  (64 + FPAD)   // 68 floats row stride

__global__ __launch_bounds__(256) void flash_attn_kernel(
    const float* __restrict__ qkv,
    float* __restrict__ ctx)
{
    extern __shared__ float sm[];
    float* Qs = sm;                  // [DH][FLD]  transposed: Qs[d][row]
    float* Ks = Qs + DH * FLD;       // [DH][FLD]  transposed: Ks[d][kv]
    float* Vs = Ks + DH * FLD;       // [FBKV][FLD] natural:  Vs[kv][d]
    float* Ps = Vs + FBKV * FLD;     // [FBQ][FLD]  natural:  Ps[row][kv]

    const int tid = threadIdx.x;
    const int bh = blockIdx.y;
    const int b = bh >> 4;
    const int h = bh & 15;
    const int q0 = blockIdx.x * FBQ;
    const int row0 = b * SEQ;

    const float* qbase  = qkv + (size_t)(row0 + q0) * 3072 + h * 64;
    const float* kbase0 = qkv + (size_t)row0 * 3072 + 1024 + h * 64;
    const float* vbase0 = qkv + (size_t)row0 * 3072 + 2048 + h * 64;

    // Load Q tile transposed, pre-scaled by dh^-0.5 = 0.125
    for (int idx = tid; idx < 64 * 16; idx += 256) {
        int r = idx >> 4;
        int c4 = (idx & 15) * 4;
        float4 v = *(const float4*)(qbase + (size_t)r * 3072 + c4);
        Qs[(c4 + 0) * FLD + r] = v.x * 0.125f;
        Qs[(c4 + 1) * FLD + r] = v.y * 0.125f;
        Qs[(c4 + 2) * FLD + r] = v.z * 0.125f;
        Qs[(c4 + 3) * FLD + r] = v.w * 0.125f;
    }

    const int tr = (tid >> 4) * 4;   // query row base (0..60)
    const int tc = (tid & 15) * 4;   // col base (kv cols for S, dh cols for O)

    float o[4][4] = {};
    float m_i[4] = {-1e30f, -1e30f, -1e30f, -1e30f};
    float l_i[4] = {0.f, 0.f, 0.f, 0.f};

    for (int t0 = 0; t0 < SEQ; t0 += FBKV) {
        __syncthreads();  // prev iter done with Ks/Vs/Ps (and Q load visible on iter 0)

        const float* kb = kbase0 + (size_t)t0 * 3072;
        const float* vb = vbase0 + (size_t)t0 * 3072;
        for (int idx = tid; idx < 64 * 16; idx += 256) {
            int r = idx >> 4;
            int c4 = (idx & 15) * 4;
            float4 kv4 = *(const float4*)(kb + (size_t)r * 3072 + c4);
            Ks[(c4 + 0) * FLD + r] = kv4.x;
            Ks[(c4 + 1) * FLD + r] = kv4.y;
            Ks[(c4 + 2) * FLD + r] = kv4.z;
            Ks[(c4 + 3) * FLD + r] = kv4.w;
            *(float4*)(Vs + (size_t)r * FLD + c4) = *(const float4*)(vb + (size_t)r * 3072 + c4);
        }
        __syncthreads();

        // S = Q @ K^T   (4x4 per thread)
        float s[4][4] = {};
#pragma unroll 16
        for (int d = 0; d < DH; d++) {
            float4 qv = *(const float4*)(Qs + d * FLD + tr);
            float4 kv4 = *(const float4*)(Ks + d * FLD + tc);
            float rq[4] = {qv.x, qv.y, qv.z, qv.w};
            float rk[4] = {kv4.x, kv4.y, kv4.z, kv4.w};
#pragma unroll
            for (int i = 0; i < 4; i++)
#pragma unroll
                for (int j = 0; j < 4; j++)
                    s[i][j] += rq[i] * rk[j];
        }

        // Online softmax (row groups of 16 lanes share a row)
#pragma unroll
        for (int i = 0; i < 4; i++) {
            float rmax = fmaxf(fmaxf(s[i][0], s[i][1]), fmaxf(s[i][2], s[i][3]));
            rmax = fmaxf(rmax, __shfl_xor_sync(0xffffffffu, rmax, 8));
            rmax = fmaxf(rmax, __shfl_xor_sync(0xffffffffu, rmax, 4));
            rmax = fmaxf(rmax, __shfl_xor_sync(0xffffffffu, rmax, 2));
            rmax = fmaxf(rmax, __shfl_xor_sync(0xffffffffu, rmax, 1));

            float mnew = fmaxf(m_i[i], rmax);
            float corr = __expf(m_i[i] - mnew);
            m_i[i] = mnew;

            float rsum = 0.f;
#pragma unroll
            for (int j = 0; j < 4; j++) {
                float p = __expf(s[i][j] - mnew);
                s[i][j] = p;
                rsum += p;
            }
            rsum += __shfl_xor_sync(0xffffffffu, rsum, 8);
            rsum += __shfl_xor_sync(0xffffffffu, rsum, 4);
            rsum += __shfl_xor_sync(0xffffffffu, rsum, 2);
            rsum += __shfl_xor_sync(0xffffffffu, rsum, 1);

            l_i[i] = l_i[i] * corr + rsum;
#pragma unroll
            for (int j = 0; j < 4; j++) o[i][j] *= corr;
        }

        // Stage P to smem (natural layout, float4 stores, conflict-free)
#pragma unroll
        for (int i = 0; i < 4; i++) {
            float4 pv = make_float4(s[i][0], s[i][1], s[i][2], s[i][3]);
            *(float4*)(Ps + (size_t)(tr + i) * FLD + tc) = pv;
        }
        __syncthreads();

        // O += P @ V
#pragma unroll 16
        for (int kv = 0; kv < FBKV; kv++) {
            float rp[4];
#pragma unroll
            for (int i = 0; i < 4; i++) rp[i] = Ps[(size_t)(tr + i) * FLD + kv];
            float4 vv = *(const float4*)(Vs + (size_t)kv * FLD + tc);
            float rv[4] = {vv.x, vv.y, vv.z, vv.w};
#pragma unroll
            for (int i = 0; i < 4; i++)
#pragma unroll
                for (int j = 0; j < 4; j++)
                    o[i][j] += rp[i] * rv[j];
        }
    }

    // Normalize and write ctx
#pragma unroll
    for (int i = 0; i < 4; i++) {
        float inv = 1.0f / l_i[i];
        float4 v;
        v.x = o[i][0] * inv;
        v.y = o[i][1] * inv;
        v.z = o[i][2] * inv;
        v.w = o[i][3] * inv;
        *(float4*)(ctx + (size_t)(row0 + q0 + tr + i) * D_MODEL + h * 64 + tc) = v;
    }
}

// ---------------------------------------------------------------------------
// Launch
// ---------------------------------------------------------------------------
extern "C" void kernel_launch(void* const* d_in, const int* in_sizes, int n_in,
                              void* d_out, int out_size)
{
    const float* x      = (const float*)d_in[0];
    const float* w_qkv  = (const float*)d_in[1];
    const float* b_qkv  = (const float*)d_in[2];
    const float* w_proj = (const float*)d_in[3];
    const float* b_proj = (const float*)d_in[4];
    float* out = (float*)d_out;

    float *qkv = nullptr, *ctx = nullptr;
    cudaGetSymbolAddress((void**)&qkv, g_qkv);
    cudaGetSymbolAddress((void**)&ctx, g_ctx);

    // 1) QKV GEMM: [8192,1024] @ [1024,3072] + bias -> g_qkv
    {
        dim3 grid((3 * D_MODEL) / GBN, NTOK / GBM);
        sgemm_bias_kernel<<<grid, 256>>>(NTOK, 3 * D_MODEL, D_MODEL, x, w_qkv, b_qkv, qkv);
    }

    // 2) Flash attention -> g_ctx
    {
        const int smem_bytes = 4 * 64 * FLD * (int)sizeof(float);  // 69632
        cudaFuncSetAttribute(flash_attn_kernel,
                             cudaFuncAttributeMaxDynamicSharedMemorySize, smem_bytes);
        dim3 grid(SEQ / FBQ, BATCH * HEADS);
        flash_attn_kernel<<<grid, 256, smem_bytes>>>(qkv, ctx);
    }

    // 3) Output projection: [8192,1024] @ [1024,1024] + bias -> out
    {
        dim3 grid(D_MODEL / GBN, NTOK / GBM);
        sgemm_bias_kernel<<<grid, 256>>>(NTOK, D_MODEL, D_MODEL, ctx, w_proj, b_proj, out);
    }
}

// round 3
// speedup vs baseline: 1.3528x; 1.3528x over previous
#include <cuda_runtime.h>
#include <cuda_bf16.h>
#include <cstdint>

#define D_MODEL 1024
#define HEADS   16
#define DH      64
#define BATCH   4
#define SEQ     2048
#define NTOK    (BATCH * SEQ)   // 8192

// ---------------- scratch (device globals; no runtime alloc allowed) -------
__device__ float g_qkv[(size_t)NTOK * 3 * D_MODEL]; // fp32 [8192,3072]
__device__ float g_ctx[(size_t)NTOK * D_MODEL];     // fp32 [8192,1024]

__device__ __nv_bfloat16 g_xhi[(size_t)NTOK * D_MODEL];
__device__ __nv_bfloat16 g_xlo[(size_t)NTOK * D_MODEL];
__device__ __nv_bfloat16 g_chi[(size_t)NTOK * D_MODEL];
__device__ __nv_bfloat16 g_clo[(size_t)NTOK * D_MODEL];
__device__ __nv_bfloat16 g_wqhi[(size_t)3 * D_MODEL * D_MODEL]; // [3072,1024] = Wqkv^T
__device__ __nv_bfloat16 g_wqlo[(size_t)3 * D_MODEL * D_MODEL];
__device__ __nv_bfloat16 g_wphi[(size_t)D_MODEL * D_MODEL];     // [1024,1024] = Wproj^T
__device__ __nv_bfloat16 g_wplo[(size_t)D_MODEL * D_MODEL];

// ---------------------------------------------------------------------------
// Helpers (portable ISA only: works on .target sm_103 without 'a' suffix)
// ---------------------------------------------------------------------------
__device__ __forceinline__ uint32_t smem_u32(const void* p) {
    uint32_t a;
    asm("{ .reg .u64 t; cvta.to.shared.u64 t, %1; cvt.u32.u64 %0, t; }"
        : "=r"(a) : "l"(p));
    return a;
}

__device__ __forceinline__ void cp16(uint32_t saddr, const void* gaddr) {
    asm volatile("cp.async.cg.shared.global [%0], [%1], 16;"
        :: "r"(saddr), "l"(gaddr));
}
#define CP_COMMIT() asm volatile("cp.async.commit_group;")
#define CP_WAIT(n)  asm volatile("cp.async.wait_group %0;" :: "n"(n))

__device__ __forceinline__ void ldm4(uint32_t* r, uint32_t a) {
    asm volatile("ldmatrix.sync.aligned.m8n8.x4.shared.b16 {%0,%1,%2,%3}, [%4];"
        : "=r"(r[0]), "=r"(r[1]), "=r"(r[2]), "=r"(r[3]) : "r"(a));
}

__device__ __forceinline__ void mma16816(float* c, const uint32_t* a, const uint32_t* b) {
    asm volatile(
        "mma.sync.aligned.m16n8k16.row.col.f32.bf16.bf16.f32 "
        "{%0,%1,%2,%3}, {%4,%5,%6,%7}, {%8,%9}, {%0,%1,%2,%3};"
        : "+f"(c[0]), "+f"(c[1]), "+f"(c[2]), "+f"(c[3])
        : "r"(a[0]), "r"(a[1]), "r"(a[2]), "r"(a[3]), "r"(b[0]), "r"(b[1]));
}

__device__ __forceinline__ uint32_t pkbf(__nv_bfloat16 a, __nv_bfloat16 b) {
    __nv_bfloat162 t = __halves2bfloat162(a, b);
    return *reinterpret_cast<uint32_t*>(&t);
}

// ---------------------------------------------------------------------------
// Conversion kernels: fp32 -> bf16 hi/lo split
// ---------------------------------------------------------------------------
__global__ __launch_bounds__(256) void convert_hilo(
    const float4* __restrict__ in, uint2* __restrict__ hi, uint2* __restrict__ lo, int n4)
{
    int i = blockIdx.x * 256 + threadIdx.x;
    if (i >= n4) return;
    float4 v = in[i];
    __nv_bfloat16 h0 = __float2bfloat16(v.x);
    __nv_bfloat16 h1 = __float2bfloat16(v.y);
    __nv_bfloat16 h2 = __float2bfloat16(v.z);
    __nv_bfloat16 h3 = __float2bfloat16(v.w);
    __nv_bfloat16 l0 = __float2bfloat16(v.x - __bfloat162float(h0));
    __nv_bfloat16 l1 = __float2bfloat16(v.y - __bfloat162float(h1));
    __nv_bfloat16 l2 = __float2bfloat16(v.z - __bfloat162float(h2));
    __nv_bfloat16 l3 = __float2bfloat16(v.w - __bfloat162float(h3));
    hi[i] = make_uint2(pkbf(h0, h1), pkbf(h2, h3));
    lo[i] = make_uint2(pkbf(l0, l1), pkbf(l2, l3));
}

// W [K,N] fp32 row-major -> T [N,K] bf16 hi/lo (transpose + split)
__global__ __launch_bounds__(256) void transpose_hilo(
    const float* __restrict__ W, int K, int N,
    __nv_bfloat16* __restrict__ Thi, __nv_bfloat16* __restrict__ Tlo)
{
    __shared__ float tile[32][33];
    int kb = blockIdx.y * 32, nb = blockIdx.x * 32;
    int tx = threadIdx.x, ty = threadIdx.y;  // 32 x 8
#pragma unroll
    for (int i = 0; i < 32; i += 8)
        tile[ty + i][tx] = W[(size_t)(kb + ty + i) * N + nb + tx];
    __syncthreads();
#pragma unroll
    for (int i = 0; i < 32; i += 8) {
        int n = nb + ty + i, k = kb + tx;
        float v = tile[tx][ty + i];
        __nv_bfloat16 h = __float2bfloat16(v);
        Thi[(size_t)n * K + k] = h;
        Tlo[(size_t)n * K + k] = __float2bfloat16(v - __bfloat162float(h));
    }
}

// ---------------------------------------------------------------------------
// HMMA bf16x3 GEMM: C[M,N] = (Ahi+Alo)[M,K] @ (Bhi+Blo)[N,K]^T + bias
// CTA tile 128x128, K-chunk 32, 8 warps (warp tile 32x64), cp.async dbl-buffer.
// Smem rows padded to 80B (40 bf16) -> conflict-free ldmatrix.
// ---------------------------------------------------------------------------
#define SROWB    80            // bytes per smem row
#define TILEB    (128 * SROWB) // 10240 bytes per 128x32 bf16 tile
#define STAGEB   (4 * TILEB)   // Ahi, Alo, Bhi, Blo
#define GEMM_SMEM (2 * STAGEB) // 81920

__global__ __launch_bounds__(256) void gemm_mma_bf16x3(
    int M, int N, int K,
    const __nv_bfloat16* __restrict__ Ahi, const __nv_bfloat16* __restrict__ Alo,
    const __nv_bfloat16* __restrict__ Bhi, const __nv_bfloat16* __restrict__ Blo,
    const float* __restrict__ bias, float* __restrict__ C)
{
    extern __shared__ char smem[];
    const uint32_t sb = smem_u32(smem);

    const int tid = threadIdx.x;
    const int lane = tid & 31;
    const int wid = tid >> 5;
    const int warpM = wid & 3;   // 4 warps over M (32 rows each)
    const int warpN = wid >> 2;  // 2 warps over N (64 cols each)

    const size_t arow0 = (size_t)blockIdx.y * 128 * K;
    const size_t brow0 = (size_t)blockIdx.x * 128 * K;

    // loader indices: 512 x 16B units per tile, 2 per thread
    const int ldRow = tid >> 2;        // 0..63 (2 passes -> 128 rows)
    const int ldKq  = (tid & 3) * 8;   // bf16 col: 0,8,16,24

    float acc[2][8][4] = {};

    const int NCH = K / 32;

    // ---- issue chunk c into stage s
    auto issue = [&](int c, int s) {
        const int k0 = c * 32;
        const uint32_t st = sb + s * STAGEB;
#pragma unroll
        for (int p = 0; p < 2; p++) {
            const int row = ldRow + p * 64;
            const uint32_t soff = row * SROWB + ldKq * 2;
            const size_t goff = (size_t)row * K + k0 + ldKq;
            cp16(st + 0 * TILEB + soff, Ahi + arow0 + goff);
            cp16(st + 1 * TILEB + soff, Alo + arow0 + goff);
            cp16(st + 2 * TILEB + soff, Bhi + brow0 + goff);
            cp16(st + 3 * TILEB + soff, Blo + brow0 + goff);
        }
    };

    issue(0, 0);
    CP_COMMIT();

    for (int c = 0; c < NCH; c++) {
        if (c + 1 < NCH) {
            issue(c + 1, (c + 1) & 1);
            CP_COMMIT();
            CP_WAIT(1);
        } else {
            CP_WAIT(0);
        }
        __syncthreads();

        const uint32_t st  = sb + (c & 1) * STAGEB;
        const uint32_t sAh = st;
        const uint32_t sAl = st + TILEB;
        const uint32_t sBh = st + 2 * TILEB;
        const uint32_t sBl = st + 3 * TILEB;

#pragma unroll
        for (int ks = 0; ks < 32; ks += 16) {
            // A fragments: 2 m16 tiles, hi + lo
            uint32_t ahi[2][4], alo[2][4];
            const int aRow = warpM * 32 + (lane & 15);
            const int aCol = ks + ((lane >> 4) << 3);
#pragma unroll
            for (int mt = 0; mt < 2; mt++) {
                const uint32_t off = (uint32_t)(aRow + mt * 16) * SROWB + aCol * 2;
                ldm4(ahi[mt], sAh + off);
                ldm4(alo[mt], sAl + off);
            }
            // B fragments: 4 ldmatrix.x4, each covers two n8 tiles; hi + lo
            uint32_t bhi[4][4], blo[4][4];
            const int bN = warpN * 64 + ((lane >> 4) << 3) + (lane & 7);
            const int bK = ks + (((lane >> 3) & 1) << 3);
#pragma unroll
            for (int ntp = 0; ntp < 4; ntp++) {
                const uint32_t off = (uint32_t)(bN + ntp * 16) * SROWB + bK * 2;
                ldm4(bhi[ntp], sBh + off);
                ldm4(blo[ntp], sBl + off);
            }
            // MMAs: hi*hi + hi*lo + lo*hi
#pragma unroll
            for (int mt = 0; mt < 2; mt++) {
#pragma unroll
                for (int nt = 0; nt < 8; nt++) {
                    const uint32_t* bh = &bhi[nt >> 1][(nt & 1) * 2];
                    const uint32_t* bl = &blo[nt >> 1][(nt & 1) * 2];
                    mma16816(acc[mt][nt], ahi[mt], bh);
                    mma16816(acc[mt][nt], ahi[mt], bl);
                    mma16816(acc[mt][nt], alo[mt], bh);
                }
            }
        }
        __syncthreads();
    }

    // ---- epilogue: bias + store
    const int rBase = blockIdx.y * 128 + warpM * 32 + (lane >> 2);
    const int cBase = blockIdx.x * 128 + warpN * 64 + (lane & 3) * 2;
#pragma unroll
    for (int mt = 0; mt < 2; mt++) {
#pragma unroll
        for (int nt = 0; nt < 8; nt++) {
            const int gc = cBase + nt * 8;
            const float b0 = bias[gc], b1 = bias[gc + 1];
            const int r0 = rBase + mt * 16;
            float2 v0 = make_float2(acc[mt][nt][0] + b0, acc[mt][nt][1] + b1);
            float2 v1 = make_float2(acc[mt][nt][2] + b0, acc[mt][nt][3] + b1);
            *(float2*)(C + (size_t)r0 * N + gc) = v0;
            *(float2*)(C + (size_t)(r0 + 8) * N + gc) = v1;
        }
    }
}

// ---------------------------------------------------------------------------
// Flash attention (fp32) — unchanged (known good)
// ---------------------------------------------------------------------------
#define FBQ  64
#define FBKV 64
#define FPAD 4
#define FLD  (64 + FPAD)

__global__ __launch_bounds__(256) void flash_attn_kernel(
    const float* __restrict__ qkv,
    float* __restrict__ ctx)
{
    extern __shared__ float sm[];
    float* Qs = sm;
    float* Ks = Qs + DH * FLD;
    float* Vs = Ks + DH * FLD;
    float* Ps = Vs + FBKV * FLD;

    const int tid = threadIdx.x;
    const int bh = blockIdx.y;
    const int b = bh >> 4;
    const int h = bh & 15;
    const int q0 = blockIdx.x * FBQ;
    const int row0 = b * SEQ;

    const float* qbase  = qkv + (size_t)(row0 + q0) * 3072 + h * 64;
    const float* kbase0 = qkv + (size_t)row0 * 3072 + 1024 + h * 64;
    const float* vbase0 = qkv + (size_t)row0 * 3072 + 2048 + h * 64;

    for (int idx = tid; idx < 64 * 16; idx += 256) {
        int r = idx >> 4;
        int c4 = (idx & 15) * 4;
        float4 v = *(const float4*)(qbase + (size_t)r * 3072 + c4);
        Qs[(c4 + 0) * FLD + r] = v.x * 0.125f;
        Qs[(c4 + 1) * FLD + r] = v.y * 0.125f;
        Qs[(c4 + 2) * FLD + r] = v.z * 0.125f;
        Qs[(c4 + 3) * FLD + r] = v.w * 0.125f;
    }

    const int tr = (tid >> 4) * 4;
    const int tc = (tid & 15) * 4;

    float o[4][4] = {};
    float m_i[4] = {-1e30f, -1e30f, -1e30f, -1e30f};
    float l_i[4] = {0.f, 0.f, 0.f, 0.f};

    for (int t0 = 0; t0 < SEQ; t0 += FBKV) {
        __syncthreads();

        const float* kb = kbase0 + (size_t)t0 * 3072;
        const float* vb = vbase0 + (size_t)t0 * 3072;
        for (int idx = tid; idx < 64 * 16; idx += 256) {
            int r = idx >> 4;
            int c4 = (idx & 15) * 4;
            float4 kv4 = *(const float4*)(kb + (size_t)r * 3072 + c4);
            Ks[(c4 + 0) * FLD + r] = kv4.x;
            Ks[(c4 + 1) * FLD + r] = kv4.y;
            Ks[(c4 + 2) * FLD + r] = kv4.z;
            Ks[(c4 + 3) * FLD + r] = kv4.w;
            *(float4*)(Vs + (size_t)r * FLD + c4) = *(const float4*)(vb + (size_t)r * 3072 + c4);
        }
        __syncthreads();

        float s[4][4] = {};
#pragma unroll 16
        for (int d = 0; d < DH; d++) {
            float4 qv = *(const float4*)(Qs + d * FLD + tr);
            float4 kv4 = *(const float4*)(Ks + d * FLD + tc);
            float rq[4] = {qv.x, qv.y, qv.z, qv.w};
            float rk[4] = {kv4.x, kv4.y, kv4.z, kv4.w};
#pragma unroll
            for (int i = 0; i < 4; i++)
#pragma unroll
                for (int j = 0; j < 4; j++)
                    s[i][j] += rq[i] * rk[j];
        }

#pragma unroll
        for (int i = 0; i < 4; i++) {
            float rmax = fmaxf(fmaxf(s[i][0], s[i][1]), fmaxf(s[i][2], s[i][3]));
            rmax = fmaxf(rmax, __shfl_xor_sync(0xffffffffu, rmax, 8));
            rmax = fmaxf(rmax, __shfl_xor_sync(0xffffffffu, rmax, 4));
            rmax = fmaxf(rmax, __shfl_xor_sync(0xffffffffu, rmax, 2));
            rmax = fmaxf(rmax, __shfl_xor_sync(0xffffffffu, rmax, 1));

            float mnew = fmaxf(m_i[i], rmax);
            float corr = __expf(m_i[i] - mnew);
            m_i[i] = mnew;

            float rsum = 0.f;
#pragma unroll
            for (int j = 0; j < 4; j++) {
                float p = __expf(s[i][j] - mnew);
                s[i][j] = p;
                rsum += p;
            }
            rsum += __shfl_xor_sync(0xffffffffu, rsum, 8);
            rsum += __shfl_xor_sync(0xffffffffu, rsum, 4);
            rsum += __shfl_xor_sync(0xffffffffu, rsum, 2);
            rsum += __shfl_xor_sync(0xffffffffu, rsum, 1);

            l_i[i] = l_i[i] * corr + rsum;
#pragma unroll
            for (int j = 0; j < 4; j++) o[i][j] *= corr;
        }

#pragma unroll
        for (int i = 0; i < 4; i++) {
            float4 pv = make_float4(s[i][0], s[i][1], s[i][2], s[i][3]);
            *(float4*)(Ps + (size_t)(tr + i) * FLD + tc) = pv;
        }
        __syncthreads();

#pragma unroll 16
        for (int kv = 0; kv < FBKV; kv++) {
            float rp[4];
#pragma unroll
            for (int i = 0; i < 4; i++) rp[i] = Ps[(size_t)(tr + i) * FLD + kv];
            float4 vv = *(const float4*)(Vs + (size_t)kv * FLD + tc);
            float rv[4] = {vv.x, vv.y, vv.z, vv.w};
#pragma unroll
            for (int i = 0; i < 4; i++)
#pragma unroll
                for (int j = 0; j < 4; j++)
                    o[i][j] += rp[i] * rv[j];
        }
    }

#pragma unroll
    for (int i = 0; i < 4; i++) {
        float inv = 1.0f / l_i[i];
        float4 v;
        v.x = o[i][0] * inv;
        v.y = o[i][1] * inv;
        v.z = o[i][2] * inv;
        v.w = o[i][3] * inv;
        *(float4*)(ctx + (size_t)(row0 + q0 + tr + i) * D_MODEL + h * 64 + tc) = v;
    }
}

// ---------------------------------------------------------------------------
// Launch
// ---------------------------------------------------------------------------
extern "C" void kernel_launch(void* const* d_in, const int* in_sizes, int n_in,
                              void* d_out, int out_size)
{
    const float* x      = (const float*)d_in[0];
    const float* w_qkv  = (const float*)d_in[1];
    const float* b_qkv  = (const float*)d_in[2];
    const float* w_proj = (const float*)d_in[3];
    const float* b_proj = (const float*)d_in[4];
    float* out = (float*)d_out;

    float *qkv, *ctx;
    __nv_bfloat16 *xhi, *xlo, *chi, *clo, *wqhi, *wqlo, *wphi, *wplo;
    cudaGetSymbolAddress((void**)&qkv, g_qkv);
    cudaGetSymbolAddress((void**)&ctx, g_ctx);
    cudaGetSymbolAddress((void**)&xhi, g_xhi);
    cudaGetSymbolAddress((void**)&xlo, g_xlo);
    cudaGetSymbolAddress((void**)&chi, g_chi);
    cudaGetSymbolAddress((void**)&clo, g_clo);
    cudaGetSymbolAddress((void**)&wqhi, g_wqhi);
    cudaGetSymbolAddress((void**)&wqlo, g_wqlo);
    cudaGetSymbolAddress((void**)&wphi, g_wphi);
    cudaGetSymbolAddress((void**)&wplo, g_wplo);

    const int fa_smem = 4 * 64 * FLD * (int)sizeof(float);
    cudaFuncSetAttribute(gemm_mma_bf16x3,
                         cudaFuncAttributeMaxDynamicSharedMemorySize, GEMM_SMEM);
    cudaFuncSetAttribute(flash_attn_kernel,
                         cudaFuncAttributeMaxDynamicSharedMemorySize, fa_smem);

    // 1) Convert x -> bf16 hi/lo; transpose-convert weights
    {
        int n4 = NTOK * D_MODEL / 4;
        convert_hilo<<<(n4 + 255) / 256, 256>>>((const float4*)x, (uint2*)xhi, (uint2*)xlo, n4);
        dim3 tg(3 * D_MODEL / 32, D_MODEL / 32);
        transpose_hilo<<<tg, dim3(32, 8)>>>(w_qkv, D_MODEL, 3 * D_MODEL, wqhi, wqlo);
        dim3 tp(D_MODEL / 32, D_MODEL / 32);
        transpose_hilo<<<tp, dim3(32, 8)>>>(w_proj, D_MODEL, D_MODEL, wphi, wplo);
    }

    // 2) QKV GEMM (HMMA bf16x3): [8192,1024] @ [1024,3072] + bias -> g_qkv
    {
        dim3 grid(3 * D_MODEL / 128, NTOK / 128);
        gemm_mma_bf16x3<<<grid, 256, GEMM_SMEM>>>(NTOK, 3 * D_MODEL, D_MODEL,
                                                  xhi, xlo, wqhi, wqlo, b_qkv, qkv);
    }

    // 3) Flash attention -> g_ctx
    {
        dim3 grid(SEQ / FBQ, BATCH * HEADS);
        flash_attn_kernel<<<grid, 256, fa_smem>>>(qkv, ctx);
    }

    // 4) Convert ctx -> bf16 hi/lo; proj GEMM -> out
    {
        int n4 = NTOK * D_MODEL / 4;
        convert_hilo<<<(n4 + 255) / 256, 256>>>((const float4*)ctx, (uint2*)chi, (uint2*)clo, n4);
        dim3 grid(D_MODEL / 128, NTOK / 128);
        gemm_mma_bf16x3<<<grid, 256, GEMM_SMEM>>>(NTOK, D_MODEL, D_MODEL,
                                                  chi, clo, wphi, wplo, b_proj, out);
    }
}

// round 4
// speedup vs baseline: 2.7435x; 2.0281x over previous
#include <cuda_runtime.h>
#include <cuda_bf16.h>
#include <cstdint>

#define D_MODEL 1024
#define HEADS   16
#define DH      64
#define BATCH   4
#define SEQ     2048
#define NTOK    (BATCH * SEQ)   // 8192

// ---------------- scratch (device globals; no runtime alloc allowed) -------
__device__ __nv_bfloat16 g_xhi[(size_t)NTOK * D_MODEL];
__device__ __nv_bfloat16 g_xlo[(size_t)NTOK * D_MODEL];
__device__ __nv_bfloat16 g_qkvhi[(size_t)NTOK * 3 * D_MODEL]; // [8192,3072]
__device__ __nv_bfloat16 g_qkvlo[(size_t)NTOK * 3 * D_MODEL];
__device__ __nv_bfloat16 g_chi[(size_t)NTOK * D_MODEL];
__device__ __nv_bfloat16 g_clo[(size_t)NTOK * D_MODEL];
__device__ __nv_bfloat16 g_wqhi[(size_t)3 * D_MODEL * D_MODEL]; // Wqkv^T [3072,1024]
__device__ __nv_bfloat16 g_wqlo[(size_t)3 * D_MODEL * D_MODEL];
__device__ __nv_bfloat16 g_wphi[(size_t)D_MODEL * D_MODEL];     // Wproj^T
__device__ __nv_bfloat16 g_wplo[(size_t)D_MODEL * D_MODEL];

// ---------------------------------------------------------------------------
// Helpers (portable ISA only — .target sm_103 without 'a')
// ---------------------------------------------------------------------------
__device__ __forceinline__ uint32_t smem_u32(const void* p) {
    uint32_t a;
    asm("{ .reg .u64 t; cvta.to.shared.u64 t, %1; cvt.u32.u64 %0, t; }"
        : "=r"(a) : "l"(p));
    return a;
}
__device__ __forceinline__ void cp16(uint32_t saddr, const void* gaddr) {
    asm volatile("cp.async.cg.shared.global [%0], [%1], 16;"
        :: "r"(saddr), "l"(gaddr));
}
#define CP_COMMIT() asm volatile("cp.async.commit_group;")
#define CP_WAIT(n)  asm volatile("cp.async.wait_group %0;" :: "n"(n))

__device__ __forceinline__ void ldm4(uint32_t* r, uint32_t a) {
    asm volatile("ldmatrix.sync.aligned.m8n8.x4.shared.b16 {%0,%1,%2,%3}, [%4];"
        : "=r"(r[0]), "=r"(r[1]), "=r"(r[2]), "=r"(r[3]) : "r"(a));
}
__device__ __forceinline__ void ldm4t(uint32_t* r, uint32_t a) {
    asm volatile("ldmatrix.sync.aligned.m8n8.x4.trans.shared.b16 {%0,%1,%2,%3}, [%4];"
        : "=r"(r[0]), "=r"(r[1]), "=r"(r[2]), "=r"(r[3]) : "r"(a));
}
__device__ __forceinline__ void mma16816(float* c, const uint32_t* a, const uint32_t* b) {
    asm volatile(
        "mma.sync.aligned.m16n8k16.row.col.f32.bf16.bf16.f32 "
        "{%0,%1,%2,%3}, {%4,%5,%6,%7}, {%8,%9}, {%0,%1,%2,%3};"
        : "+f"(c[0]), "+f"(c[1]), "+f"(c[2]), "+f"(c[3])
        : "r"(a[0]), "r"(a[1]), "r"(a[2]), "r"(a[3]), "r"(b[0]), "r"(b[1]));
}
__device__ __forceinline__ uint32_t pkbf(__nv_bfloat16 a, __nv_bfloat16 b) {
    __nv_bfloat162 t = __halves2bfloat162(a, b);
    return *reinterpret_cast<uint32_t*>(&t);
}
__device__ __forceinline__ uint32_t pk_hi2(float a, float b) {
    return pkbf(__float2bfloat16(a), __float2bfloat16(b));
}
__device__ __forceinline__ uint32_t pk_lo2(float a, float b) {
    __nv_bfloat16 ha = __float2bfloat16(a), hb = __float2bfloat16(b);
    return pkbf(__float2bfloat16(a - __bfloat162float(ha)),
                __float2bfloat16(b - __bfloat162float(hb)));
}

// ---------------------------------------------------------------------------
// Conversion kernels
// ---------------------------------------------------------------------------
__global__ __launch_bounds__(256) void convert_hilo(
    const float4* __restrict__ in, uint2* __restrict__ hi, uint2* __restrict__ lo, int n4)
{
    int i = blockIdx.x * 256 + threadIdx.x;
    if (i >= n4) return;
    float4 v = in[i];
    hi[i] = make_uint2(pk_hi2(v.x, v.y), pk_hi2(v.z, v.w));
    lo[i] = make_uint2(pk_lo2(v.x, v.y), pk_lo2(v.z, v.w));
}

__global__ __launch_bounds__(256) void transpose_hilo(
    const float* __restrict__ W, int K, int N,
    __nv_bfloat16* __restrict__ Thi, __nv_bfloat16* __restrict__ Tlo)
{
    __shared__ float tile[32][33];
    int kb = blockIdx.y * 32, nb = blockIdx.x * 32;
    int tx = threadIdx.x, ty = threadIdx.y;
#pragma unroll
    for (int i = 0; i < 32; i += 8)
        tile[ty + i][tx] = W[(size_t)(kb + ty + i) * N + nb + tx];
    __syncthreads();
#pragma unroll
    for (int i = 0; i < 32; i += 8) {
        int n = nb + ty + i, k = kb + tx;
        float v = tile[tx][ty + i];
        __nv_bfloat16 h = __float2bfloat16(v);
        Thi[(size_t)n * K + k] = h;
        Tlo[(size_t)n * K + k] = __float2bfloat16(v - __bfloat162float(h));
    }
}

// ---------------------------------------------------------------------------
// HMMA bf16x3 GEMM: C = (Ahi+Alo)[M,K] @ (Bhi+Blo)[N,K]^T + bias
// Output either fp32 (C) or bf16 hi/lo (Chi/Clo), selected by hilo_out.
// ---------------------------------------------------------------------------
#define SROWB    80
#define TILEB    (128 * SROWB)
#define STAGEB   (4 * TILEB)
#define GEMM_SMEM (2 * STAGEB)

__global__ __launch_bounds__(256) void gemm_mma_bf16x3(
    int M, int N, int K,
    const __nv_bfloat16* __restrict__ Ahi, const __nv_bfloat16* __restrict__ Alo,
    const __nv_bfloat16* __restrict__ Bhi, const __nv_bfloat16* __restrict__ Blo,
    const float* __restrict__ bias,
    float* __restrict__ C,
    __nv_bfloat16* __restrict__ Chi, __nv_bfloat16* __restrict__ Clo,
    int hilo_out)
{
    extern __shared__ char smem[];
    const uint32_t sb = smem_u32(smem);

    const int tid = threadIdx.x;
    const int lane = tid & 31;
    const int wid = tid >> 5;
    const int warpM = wid & 3;
    const int warpN = wid >> 2;

    const size_t arow0 = (size_t)blockIdx.y * 128 * K;
    const size_t brow0 = (size_t)blockIdx.x * 128 * K;

    const int ldRow = tid >> 2;
    const int ldKq  = (tid & 3) * 8;

    float acc[2][8][4] = {};
    const int NCH = K / 32;

    auto issue = [&](int c, int s) {
        const int k0 = c * 32;
        const uint32_t st = sb + s * STAGEB;
#pragma unroll
        for (int p = 0; p < 2; p++) {
            const int row = ldRow + p * 64;
            const uint32_t soff = row * SROWB + ldKq * 2;
            const size_t goff = (size_t)row * K + k0 + ldKq;
            cp16(st + 0 * TILEB + soff, Ahi + arow0 + goff);
            cp16(st + 1 * TILEB + soff, Alo + arow0 + goff);
            cp16(st + 2 * TILEB + soff, Bhi + brow0 + goff);
            cp16(st + 3 * TILEB + soff, Blo + brow0 + goff);
        }
    };

    issue(0, 0);
    CP_COMMIT();

    for (int c = 0; c < NCH; c++) {
        if (c + 1 < NCH) { issue(c + 1, (c + 1) & 1); CP_COMMIT(); CP_WAIT(1); }
        else CP_WAIT(0);
        __syncthreads();

        const uint32_t st  = sb + (c & 1) * STAGEB;
        const uint32_t sAh = st;
        const uint32_t sAl = st + TILEB;
        const uint32_t sBh = st + 2 * TILEB;
        const uint32_t sBl = st + 3 * TILEB;

#pragma unroll
        for (int ks = 0; ks < 32; ks += 16) {
            uint32_t ahi[2][4], alo[2][4];
            const int aRow = warpM * 32 + (lane & 15);
            const int aCol = ks + ((lane >> 4) << 3);
#pragma unroll
            for (int mt = 0; mt < 2; mt++) {
                const uint32_t off = (uint32_t)(aRow + mt * 16) * SROWB + aCol * 2;
                ldm4(ahi[mt], sAh + off);
                ldm4(alo[mt], sAl + off);
            }
            uint32_t bhi[4][4], blo[4][4];
            const int bN = warpN * 64 + ((lane >> 4) << 3) + (lane & 7);
            const int bK = ks + (((lane >> 3) & 1) << 3);
#pragma unroll
            for (int ntp = 0; ntp < 4; ntp++) {
                const uint32_t off = (uint32_t)(bN + ntp * 16) * SROWB + bK * 2;
                ldm4(bhi[ntp], sBh + off);
                ldm4(blo[ntp], sBl + off);
            }
#pragma unroll
            for (int mt = 0; mt < 2; mt++) {
#pragma unroll
                for (int nt = 0; nt < 8; nt++) {
                    const uint32_t* bh = &bhi[nt >> 1][(nt & 1) * 2];
                    const uint32_t* bl = &blo[nt >> 1][(nt & 1) * 2];
                    mma16816(acc[mt][nt], ahi[mt], bh);
                    mma16816(acc[mt][nt], ahi[mt], bl);
                    mma16816(acc[mt][nt], alo[mt], bh);
                }
            }
        }
        __syncthreads();
    }

    const int rBase = blockIdx.y * 128 + warpM * 32 + (lane >> 2);
    const int cBase = blockIdx.x * 128 + warpN * 64 + (lane & 3) * 2;
#pragma unroll
    for (int mt = 0; mt < 2; mt++) {
#pragma unroll
        for (int nt = 0; nt < 8; nt++) {
            const int gc = cBase + nt * 8;
            const float b0 = bias[gc], b1 = bias[gc + 1];
            const int r0 = rBase + mt * 16;
            float v00 = acc[mt][nt][0] + b0, v01 = acc[mt][nt][1] + b1;
            float v10 = acc[mt][nt][2] + b0, v11 = acc[mt][nt][3] + b1;
            if (!hilo_out) {
                *(float2*)(C + (size_t)r0 * N + gc) = make_float2(v00, v01);
                *(float2*)(C + (size_t)(r0 + 8) * N + gc) = make_float2(v10, v11);
            } else {
                *(uint32_t*)(Chi + (size_t)r0 * N + gc) = pk_hi2(v00, v01);
                *(uint32_t*)(Clo + (size_t)r0 * N + gc) = pk_lo2(v00, v01);
                *(uint32_t*)(Chi + (size_t)(r0 + 8) * N + gc) = pk_hi2(v10, v11);
                *(uint32_t*)(Clo + (size_t)(r0 + 8) * N + gc) = pk_lo2(v10, v11);
            }
        }
    }
}

// ---------------------------------------------------------------------------
// HMMA flash attention (bf16x3, FA2-style).
// CTA: 128 queries of one (b,h); 8 warps x 16 rows. KV tile 64, dbl-buffered.
// ---------------------------------------------------------------------------
#define ASROWB   144                 // padded row bytes (72 bf16)
#define AQ_BYTES (128 * ASROWB)      // 18432
#define AKV_BYTES (64 * ASROWB)      // 9216
#define ASTAGEB  (4 * AKV_BYTES)     // 36864
#define ATT_SMEM (2 * AQ_BYTES + 2 * ASTAGEB)  // 110592

__global__ __launch_bounds__(256) void attn_mma(
    const __nv_bfloat16* __restrict__ qkvhi,
    const __nv_bfloat16* __restrict__ qkvlo,
    __nv_bfloat16* __restrict__ chi,
    __nv_bfloat16* __restrict__ clo)
{
    extern __shared__ char smem[];
    const uint32_t sb = smem_u32(smem);
    const uint32_t sQh = sb;
    const uint32_t sQl = sb + AQ_BYTES;
    const uint32_t sKV = sb + 2 * AQ_BYTES;

    const int tid = threadIdx.x;
    const int lane = tid & 31;
    const int wid = tid >> 5;

    const int b = blockIdx.y >> 4;
    const int h = blockIdx.y & 15;
    const int q0 = blockIdx.x * 128;
    const size_t row0 = (size_t)b * SEQ;

    const size_t qoff = (row0 + q0) * 3072 + h * 64;
    const size_t koff = row0 * 3072 + 1024 + h * 64;
    const size_t voff = row0 * 3072 + 2048 + h * 64;

    // Q: 128 rows x 8 x 16B chunks, hi + lo
#pragma unroll
    for (int i = 0; i < 4; i++) {
        int idx = tid + i * 256;
        int row = idx >> 3, ch = idx & 7;
        uint32_t so = (uint32_t)row * ASROWB + ch * 16;
        size_t go = (size_t)row * 3072 + ch * 8;
        cp16(sQh + so, qkvhi + qoff + go);
        cp16(sQl + so, qkvlo + qoff + go);
    }

    auto issueKV = [&](int t, int s) {
        const uint32_t st = sKV + s * ASTAGEB;
        const size_t kvrow = (size_t)t * 64;
#pragma unroll
        for (int i = 0; i < 2; i++) {
            int idx = tid + i * 256;
            int row = idx >> 3, ch = idx & 7;
            uint32_t so = (uint32_t)row * ASROWB + ch * 16;
            size_t go = (kvrow + row) * 3072 + ch * 8;
            cp16(st + 0 * AKV_BYTES + so, qkvhi + koff + go);
            cp16(st + 1 * AKV_BYTES + so, qkvlo + koff + go);
            cp16(st + 2 * AKV_BYTES + so, qkvhi + voff + go);
            cp16(st + 3 * AKV_BYTES + so, qkvlo + voff + go);
        }
    };
    issueKV(0, 0);
    CP_COMMIT();

    uint32_t qh[4][4], ql[4][4];
    float o[8][4] = {};
    float mA = -1e30f, mB = -1e30f, lA = 0.f, lB = 0.f;

    const int bN  = ((lane >> 4) << 3) + (lane & 7);
    const int bK8 = ((lane >> 3) & 1) << 3;

    const int NT = SEQ / 64;
    for (int t = 0; t < NT; t++) {
        if (t + 1 < NT) { issueKV(t + 1, (t + 1) & 1); CP_COMMIT(); CP_WAIT(1); }
        else CP_WAIT(0);
        __syncthreads();

        const uint32_t st  = sKV + (t & 1) * ASTAGEB;
        const uint32_t sKh = st;
        const uint32_t sKl = st + AKV_BYTES;
        const uint32_t sVh = st + 2 * AKV_BYTES;
        const uint32_t sVl = st + 3 * AKV_BYTES;

        if (t == 0) {
            const int aRow = wid * 16 + (lane & 15);
            const int aC8  = (lane >> 4) << 3;
#pragma unroll
            for (int ks = 0; ks < 4; ks++) {
                uint32_t off = (uint32_t)aRow * ASROWB + (ks * 16 + aC8) * 2;
                ldm4(qh[ks], sQh + off);
                ldm4(ql[ks], sQl + off);
            }
        }

        // ---- S = Q K^T (bf16x3)
        float s[8][4] = {};
#pragma unroll
        for (int ks = 0; ks < 4; ks++) {
            uint32_t kbh[4][4], kbl[4][4];
#pragma unroll
            for (int np = 0; np < 4; np++) {
                uint32_t off = (uint32_t)(bN + np * 16) * ASROWB + (ks * 16 + bK8) * 2;
                ldm4(kbh[np], sKh + off);
                ldm4(kbl[np], sKl + off);
            }
#pragma unroll
            for (int nt = 0; nt < 8; nt++) {
                const uint32_t* bh = &kbh[nt >> 1][(nt & 1) * 2];
                const uint32_t* bl = &kbl[nt >> 1][(nt & 1) * 2];
                mma16816(s[nt], qh[ks], bh);
                mma16816(s[nt], qh[ks], bl);
                mma16816(s[nt], ql[ks], bh);
            }
        }

        // ---- online softmax (rows rA = lane>>2, rB = rA+8)
        float rmaxA = -1e30f, rmaxB = -1e30f;
#pragma unroll
        for (int nt = 0; nt < 8; nt++) {
#pragma unroll
            for (int j = 0; j < 4; j++) s[nt][j] *= 0.125f;
            rmaxA = fmaxf(rmaxA, fmaxf(s[nt][0], s[nt][1]));
            rmaxB = fmaxf(rmaxB, fmaxf(s[nt][2], s[nt][3]));
        }
        rmaxA = fmaxf(rmaxA, __shfl_xor_sync(0xffffffffu, rmaxA, 1));
        rmaxA = fmaxf(rmaxA, __shfl_xor_sync(0xffffffffu, rmaxA, 2));
        rmaxB = fmaxf(rmaxB, __shfl_xor_sync(0xffffffffu, rmaxB, 1));
        rmaxB = fmaxf(rmaxB, __shfl_xor_sync(0xffffffffu, rmaxB, 2));

        float mnA = fmaxf(mA, rmaxA), mnB = fmaxf(mB, rmaxB);
        float corrA = __expf(mA - mnA), corrB = __expf(mB - mnB);
        mA = mnA; mB = mnB;

        float rsA = 0.f, rsB = 0.f;
#pragma unroll
        for (int nt = 0; nt < 8; nt++) {
            s[nt][0] = __expf(s[nt][0] - mnA);
            s[nt][1] = __expf(s[nt][1] - mnA);
            s[nt][2] = __expf(s[nt][2] - mnB);
            s[nt][3] = __expf(s[nt][3] - mnB);
            rsA += s[nt][0] + s[nt][1];
            rsB += s[nt][2] + s[nt][3];
        }
        rsA += __shfl_xor_sync(0xffffffffu, rsA, 1);
        rsA += __shfl_xor_sync(0xffffffffu, rsA, 2);
        rsB += __shfl_xor_sync(0xffffffffu, rsB, 1);
        rsB += __shfl_xor_sync(0xffffffffu, rsB, 2);
        lA = lA * corrA + rsA;
        lB = lB * corrB + rsB;
#pragma unroll
        for (int nt = 0; nt < 8; nt++) {
            o[nt][0] *= corrA; o[nt][1] *= corrA;
            o[nt][2] *= corrB; o[nt][3] *= corrB;
        }

        // ---- O += P V (P hi/lo from registers, V via ldmatrix.trans)
#pragma unroll
        for (int t4 = 0; t4 < 4; t4++) {
            uint32_t ph[4], pl[4];
            {
                const float* s0 = s[2 * t4];
                const float* s1 = s[2 * t4 + 1];
                ph[0] = pk_hi2(s0[0], s0[1]);  pl[0] = pk_lo2(s0[0], s0[1]);
                ph[1] = pk_hi2(s0[2], s0[3]);  pl[1] = pk_lo2(s0[2], s0[3]);
                ph[2] = pk_hi2(s1[0], s1[1]);  pl[2] = pk_lo2(s1[0], s1[1]);
                ph[3] = pk_hi2(s1[2], s1[3]);  pl[3] = pk_lo2(s1[2], s1[3]);
            }
#pragma unroll
            for (int np = 0; np < 4; np++) {
                uint32_t vh[4], vl[4];
                uint32_t off = (uint32_t)(t4 * 16 + (lane & 15)) * ASROWB
                             + (np * 16 + ((lane >> 4) << 3)) * 2;
                ldm4t(vh, sVh + off);
                ldm4t(vl, sVl + off);
                mma16816(o[2 * np],     ph, &vh[0]);
                mma16816(o[2 * np],     ph, &vl[0]);
                mma16816(o[2 * np],     pl, &vh[0]);
                mma16816(o[2 * np + 1], ph, &vh[2]);
                mma16816(o[2 * np + 1], ph, &vl[2]);
                mma16816(o[2 * np + 1], pl, &vh[2]);
            }
        }
        __syncthreads();
    }

    // ---- epilogue: normalize, split hi/lo, store ctx
    const float ivA = 1.f / lA, ivB = 1.f / lB;
    const size_t tokA = row0 + q0 + wid * 16 + (lane >> 2);
    const size_t tokB = tokA + 8;
#pragma unroll
    for (int nt = 0; nt < 8; nt++) {
        const int col = h * 64 + nt * 8 + (lane & 3) * 2;
        float v0 = o[nt][0] * ivA, v1 = o[nt][1] * ivA;
        float v2 = o[nt][2] * ivB, v3 = o[nt][3] * ivB;
        *(uint32_t*)(chi + tokA * D_MODEL + col) = pk_hi2(v0, v1);
        *(uint32_t*)(clo + tokA * D_MODEL + col) = pk_lo2(v0, v1);
        *(uint32_t*)(chi + tokB * D_MODEL + col) = pk_hi2(v2, v3);
        *(uint32_t*)(clo + tokB * D_MODEL + col) = pk_lo2(v2, v3);
    }
}

// ---------------------------------------------------------------------------
// Launch
// ---------------------------------------------------------------------------
extern "C" void kernel_launch(void* const* d_in, const int* in_sizes, int n_in,
                              void* d_out, int out_size)
{
    const float* x      = (const float*)d_in[0];
    const float* w_qkv  = (const float*)d_in[1];
    const float* b_qkv  = (const float*)d_in[2];
    const float* w_proj = (const float*)d_in[3];
    const float* b_proj = (const float*)d_in[4];
    float* out = (float*)d_out;

    __nv_bfloat16 *xhi, *xlo, *qkvhi, *qkvlo, *chi, *clo, *wqhi, *wqlo, *wphi, *wplo;
    cudaGetSymbolAddress((void**)&xhi, g_xhi);
    cudaGetSymbolAddress((void**)&xlo, g_xlo);
    cudaGetSymbolAddress((void**)&qkvhi, g_qkvhi);
    cudaGetSymbolAddress((void**)&qkvlo, g_qkvlo);
    cudaGetSymbolAddress((void**)&chi, g_chi);
    cudaGetSymbolAddress((void**)&clo, g_clo);
    cudaGetSymbolAddress((void**)&wqhi, g_wqhi);
    cudaGetSymbolAddress((void**)&wqlo, g_wqlo);
    cudaGetSymbolAddress((void**)&wphi, g_wphi);
    cudaGetSymbolAddress((void**)&wplo, g_wplo);

    cudaFuncSetAttribute(gemm_mma_bf16x3,
                         cudaFuncAttributeMaxDynamicSharedMemorySize, GEMM_SMEM);
    cudaFuncSetAttribute(attn_mma,
                         cudaFuncAttributeMaxDynamicSharedMemorySize, ATT_SMEM);

    // 1) x -> bf16 hi/lo; weights transpose+split
    {
        int n4 = NTOK * D_MODEL / 4;
        convert_hilo<<<(n4 + 255) / 256, 256>>>((const float4*)x, (uint2*)xhi, (uint2*)xlo, n4);
        dim3 tg(3 * D_MODEL / 32, D_MODEL / 32);
        transpose_hilo<<<tg, dim3(32, 8)>>>(w_qkv, D_MODEL, 3 * D_MODEL, wqhi, wqlo);
        dim3 tp(D_MODEL / 32, D_MODEL / 32);
        transpose_hilo<<<tp, dim3(32, 8)>>>(w_proj, D_MODEL, D_MODEL, wphi, wplo);
    }

    // 2) QKV GEMM -> bf16 hi/lo qkv
    {
        dim3 grid(3 * D_MODEL / 128, NTOK / 128);
        gemm_mma_bf16x3<<<grid, 256, GEMM_SMEM>>>(NTOK, 3 * D_MODEL, D_MODEL,
                                                  xhi, xlo, wqhi, wqlo, b_qkv,
                                                  nullptr, qkvhi, qkvlo, 1);
    }

    // 3) HMMA flash attention -> bf16 hi/lo ctx
    {
        dim3 grid(SEQ / 128, BATCH * HEADS);
        attn_mma<<<grid, 256, ATT_SMEM>>>(qkvhi, qkvlo, chi, clo);
    }

    // 4) Proj GEMM -> fp32 out
    {
        dim3 grid(D_MODEL / 128, NTOK / 128);
        gemm_mma_bf16x3<<<grid, 256, GEMM_SMEM>>>(NTOK, D_MODEL, D_MODEL,
                                                  chi, clo, wphi, wplo, b_proj,
                                                  out, nullptr, nullptr, 0);
    }
}

// round 5
// speedup vs baseline: 2.9501x; 1.0753x over previous
#include <cuda_runtime.h>
#include <cuda_bf16.h>
#include <cstdint>

#define D_MODEL 1024
#define HEADS   16
#define DH      64
#define BATCH   4
#define SEQ     2048
#define NTOK    (BATCH * SEQ)   // 8192

// ---------------- scratch (device globals; no runtime alloc allowed) -------
__device__ __nv_bfloat16 g_xhi[(size_t)NTOK * D_MODEL];
__device__ __nv_bfloat16 g_xlo[(size_t)NTOK * D_MODEL];
__device__ __nv_bfloat16 g_qkvhi[(size_t)NTOK * 3 * D_MODEL]; // [8192,3072]
__device__ __nv_bfloat16 g_qkvlo[(size_t)NTOK * 3 * D_MODEL];
__device__ __nv_bfloat16 g_chi[(size_t)NTOK * D_MODEL];
__device__ __nv_bfloat16 g_clo[(size_t)NTOK * D_MODEL];
__device__ __nv_bfloat16 g_wqhi[(size_t)3 * D_MODEL * D_MODEL]; // Wqkv^T [3072,1024]
__device__ __nv_bfloat16 g_wqlo[(size_t)3 * D_MODEL * D_MODEL];
__device__ __nv_bfloat16 g_wphi[(size_t)D_MODEL * D_MODEL];     // Wproj^T
__device__ __nv_bfloat16 g_wplo[(size_t)D_MODEL * D_MODEL];

// ---------------------------------------------------------------------------
// Helpers (portable ISA only — .target sm_103 without 'a')
// ---------------------------------------------------------------------------
__device__ __forceinline__ uint32_t smem_u32(const void* p) {
    uint32_t a;
    asm("{ .reg .u64 t; cvta.to.shared.u64 t, %1; cvt.u32.u64 %0, t; }"
        : "=r"(a) : "l"(p));
    return a;
}
__device__ __forceinline__ void cp16(uint32_t saddr, const void* gaddr) {
    asm volatile("cp.async.cg.shared.global [%0], [%1], 16;"
        :: "r"(saddr), "l"(gaddr));
}
#define CP_COMMIT() asm volatile("cp.async.commit_group;")
#define CP_WAIT(n)  asm volatile("cp.async.wait_group %0;" :: "n"(n))

__device__ __forceinline__ void ldm4(uint32_t* r, uint32_t a) {
    asm volatile("ldmatrix.sync.aligned.m8n8.x4.shared.b16 {%0,%1,%2,%3}, [%4];"
        : "=r"(r[0]), "=r"(r[1]), "=r"(r[2]), "=r"(r[3]) : "r"(a));
}
__device__ __forceinline__ void ldm4t(uint32_t* r, uint32_t a) {
    asm volatile("ldmatrix.sync.aligned.m8n8.x4.trans.shared.b16 {%0,%1,%2,%3}, [%4];"
        : "=r"(r[0]), "=r"(r[1]), "=r"(r[2]), "=r"(r[3]) : "r"(a));
}
__device__ __forceinline__ void mma16816(float* c, const uint32_t* a, const uint32_t* b) {
    asm volatile(
        "mma.sync.aligned.m16n8k16.row.col.f32.bf16.bf16.f32 "
        "{%0,%1,%2,%3}, {%4,%5,%6,%7}, {%8,%9}, {%0,%1,%2,%3};"
        : "+f"(c[0]), "+f"(c[1]), "+f"(c[2]), "+f"(c[3])
        : "r"(a[0]), "r"(a[1]), "r"(a[2]), "r"(a[3]), "r"(b[0]), "r"(b[1]));
}
__device__ __forceinline__ uint32_t pkbf(__nv_bfloat16 a, __nv_bfloat16 b) {
    __nv_bfloat162 t = __halves2bfloat162(a, b);
    return *reinterpret_cast<uint32_t*>(&t);
}
__device__ __forceinline__ uint32_t pk_hi2(float a, float b) {
    return pkbf(__float2bfloat16(a), __float2bfloat16(b));
}
__device__ __forceinline__ uint32_t pk_lo2(float a, float b) {
    __nv_bfloat16 ha = __float2bfloat16(a), hb = __float2bfloat16(b);
    return pkbf(__float2bfloat16(a - __bfloat162float(ha)),
                __float2bfloat16(b - __bfloat162float(hb)));
}

// swizzled offset in a 128x32bf16 tile: 64B rows, 16B chunks, conflict-free
__device__ __forceinline__ uint32_t gswz(int row, int chunk) {
    return (uint32_t)row * 64 + ((chunk ^ ((row >> 1) & 3)) << 4);
}

// ---------------------------------------------------------------------------
// Conversion kernels
// ---------------------------------------------------------------------------
__global__ __launch_bounds__(256) void convert_hilo(
    const float4* __restrict__ in, uint2* __restrict__ hi, uint2* __restrict__ lo, int n4)
{
    int i = blockIdx.x * 256 + threadIdx.x;
    if (i >= n4) return;
    float4 v = in[i];
    hi[i] = make_uint2(pk_hi2(v.x, v.y), pk_hi2(v.z, v.w));
    lo[i] = make_uint2(pk_lo2(v.x, v.y), pk_lo2(v.z, v.w));
}

__global__ __launch_bounds__(256) void transpose_hilo(
    const float* __restrict__ W, int K, int N,
    __nv_bfloat16* __restrict__ Thi, __nv_bfloat16* __restrict__ Tlo)
{
    __shared__ float tile[32][33];
    int kb = blockIdx.y * 32, nb = blockIdx.x * 32;
    int tx = threadIdx.x, ty = threadIdx.y;
#pragma unroll
    for (int i = 0; i < 32; i += 8)
        tile[ty + i][tx] = W[(size_t)(kb + ty + i) * N + nb + tx];
    __syncthreads();
#pragma unroll
    for (int i = 0; i < 32; i += 8) {
        int n = nb + ty + i, k = kb + tx;
        float v = tile[tx][ty + i];
        __nv_bfloat16 h = __float2bfloat16(v);
        Thi[(size_t)n * K + k] = h;
        Tlo[(size_t)n * K + k] = __float2bfloat16(v - __bfloat162float(h));
    }
}

// ---------------------------------------------------------------------------
// HMMA bf16x3 GEMM: C = (Ahi+Alo)[M,K] @ (Bhi+Blo)[N,K]^T + bias
// 128x128 CTA tile, K-chunk 32, swizzled 64B rows, 3-stage cp.async.
// ---------------------------------------------------------------------------
#define TILEB    8192              // 128 rows x 64B (swizzled, no pad)
#define STAGEB   (4 * TILEB)       // Ahi, Alo, Bhi, Blo = 32768
#define NSTAGE   3
#define GEMM_SMEM (NSTAGE * STAGEB)  // 98304

__global__ __launch_bounds__(256) void gemm_mma_bf16x3(
    int M, int N, int K,
    const __nv_bfloat16* __restrict__ Ahi, const __nv_bfloat16* __restrict__ Alo,
    const __nv_bfloat16* __restrict__ Bhi, const __nv_bfloat16* __restrict__ Blo,
    const float* __restrict__ bias,
    float* __restrict__ C,
    __nv_bfloat16* __restrict__ Chi, __nv_bfloat16* __restrict__ Clo,
    int hilo_out)
{
    extern __shared__ char smem[];
    const uint32_t sb = smem_u32(smem);

    const int tid = threadIdx.x;
    const int lane = tid & 31;
    const int wid = tid >> 5;
    const int warpM = wid & 3;
    const int warpN = wid >> 2;

    const size_t arow0 = (size_t)blockIdx.y * 128 * K;
    const size_t brow0 = (size_t)blockIdx.x * 128 * K;

    const int ldRow = tid >> 2;        // 0..63
    const int ldCh  = tid & 3;         // 16B chunk 0..3

    float acc[2][8][4] = {};
    const int NCH = K / 32;

    auto issue = [&](int c, int s) {
        const int k0 = c * 32;
        const uint32_t st = sb + s * STAGEB;
#pragma unroll
        for (int p = 0; p < 2; p++) {
            const int row = ldRow + p * 64;
            const uint32_t soff = gswz(row, ldCh);
            const size_t goff = (size_t)row * K + k0 + ldCh * 8;
            cp16(st + 0 * TILEB + soff, Ahi + arow0 + goff);
            cp16(st + 1 * TILEB + soff, Alo + arow0 + goff);
            cp16(st + 2 * TILEB + soff, Bhi + brow0 + goff);
            cp16(st + 3 * TILEB + soff, Blo + brow0 + goff);
        }
    };

    issue(0, 0); CP_COMMIT();
    issue(1, 1); CP_COMMIT();

    for (int c = 0; c < NCH; c++) {
        if (c + 2 < NCH) { issue(c + 2, (c + 2) % NSTAGE); CP_COMMIT(); CP_WAIT(2); }
        else if (c + 1 < NCH) CP_WAIT(1);
        else CP_WAIT(0);
        __syncthreads();

        const uint32_t st  = sb + (c % NSTAGE) * STAGEB;
        const uint32_t sAh = st;
        const uint32_t sAl = st + TILEB;
        const uint32_t sBh = st + 2 * TILEB;
        const uint32_t sBl = st + 3 * TILEB;

#pragma unroll
        for (int ks = 0; ks < 2; ks++) {   // two k16 halves of the chunk
            uint32_t ahi[2][4], alo[2][4];
            const int aRow = warpM * 32 + (lane & 15);
            const int aCh  = ks * 2 + (lane >> 4);    // chunk 0..3
#pragma unroll
            for (int mt = 0; mt < 2; mt++) {
                const uint32_t off = gswz(aRow + mt * 16, aCh);
                ldm4(ahi[mt], sAh + off);
                ldm4(alo[mt], sAl + off);
            }
            uint32_t bhi[4][4], blo[4][4];
            const int bRow = warpN * 64 + ((lane >> 4) << 3) + (lane & 7);
            const int bCh  = ks * 2 + ((lane >> 3) & 1);
#pragma unroll
            for (int ntp = 0; ntp < 4; ntp++) {
                const uint32_t off = gswz(bRow + ntp * 16, bCh);
                ldm4(bhi[ntp], sBh + off);
                ldm4(blo[ntp], sBl + off);
            }
#pragma unroll
            for (int mt = 0; mt < 2; mt++) {
#pragma unroll
                for (int nt = 0; nt < 8; nt++) {
                    const uint32_t* bh = &bhi[nt >> 1][(nt & 1) * 2];
                    const uint32_t* bl = &blo[nt >> 1][(nt & 1) * 2];
                    mma16816(acc[mt][nt], ahi[mt], bh);
                    mma16816(acc[mt][nt], ahi[mt], bl);
                    mma16816(acc[mt][nt], alo[mt], bh);
                }
            }
        }
        __syncthreads();
    }

    const int rBase = blockIdx.y * 128 + warpM * 32 + (lane >> 2);
    const int cBase = blockIdx.x * 128 + warpN * 64 + (lane & 3) * 2;
#pragma unroll
    for (int mt = 0; mt < 2; mt++) {
#pragma unroll
        for (int nt = 0; nt < 8; nt++) {
            const int gc = cBase + nt * 8;
            const float b0 = bias[gc], b1 = bias[gc + 1];
            const int r0 = rBase + mt * 16;
            float v00 = acc[mt][nt][0] + b0, v01 = acc[mt][nt][1] + b1;
            float v10 = acc[mt][nt][2] + b0, v11 = acc[mt][nt][3] + b1;
            if (!hilo_out) {
                *(float2*)(C + (size_t)r0 * N + gc) = make_float2(v00, v01);
                *(float2*)(C + (size_t)(r0 + 8) * N + gc) = make_float2(v10, v11);
            } else {
                *(uint32_t*)(Chi + (size_t)r0 * N + gc) = pk_hi2(v00, v01);
                *(uint32_t*)(Clo + (size_t)r0 * N + gc) = pk_lo2(v00, v01);
                *(uint32_t*)(Chi + (size_t)(r0 + 8) * N + gc) = pk_hi2(v10, v11);
                *(uint32_t*)(Clo + (size_t)(r0 + 8) * N + gc) = pk_lo2(v10, v11);
            }
        }
    }
}

// ---------------------------------------------------------------------------
// HMMA flash attention (bf16x3, FA2-style) — unchanged from round 4 (passing)
// ---------------------------------------------------------------------------
#define ASROWB   144
#define AQ_BYTES (128 * ASROWB)
#define AKV_BYTES (64 * ASROWB)
#define ASTAGEB  (4 * AKV_BYTES)
#define ATT_SMEM (2 * AQ_BYTES + 2 * ASTAGEB)  // 110592

__global__ __launch_bounds__(256) void attn_mma(
    const __nv_bfloat16* __restrict__ qkvhi,
    const __nv_bfloat16* __restrict__ qkvlo,
    __nv_bfloat16* __restrict__ chi,
    __nv_bfloat16* __restrict__ clo)
{
    extern __shared__ char smem[];
    const uint32_t sb = smem_u32(smem);
    const uint32_t sQh = sb;
    const uint32_t sQl = sb + AQ_BYTES;
    const uint32_t sKV = sb + 2 * AQ_BYTES;

    const int tid = threadIdx.x;
    const int lane = tid & 31;
    const int wid = tid >> 5;

    const int b = blockIdx.y >> 4;
    const int h = blockIdx.y & 15;
    const int q0 = blockIdx.x * 128;
    const size_t row0 = (size_t)b * SEQ;

    const size_t qoff = (row0 + q0) * 3072 + h * 64;
    const size_t koff = row0 * 3072 + 1024 + h * 64;
    const size_t voff = row0 * 3072 + 2048 + h * 64;

#pragma unroll
    for (int i = 0; i < 4; i++) {
        int idx = tid + i * 256;
        int row = idx >> 3, ch = idx & 7;
        uint32_t so = (uint32_t)row * ASROWB + ch * 16;
        size_t go = (size_t)row * 3072 + ch * 8;
        cp16(sQh + so, qkvhi + qoff + go);
        cp16(sQl + so, qkvlo + qoff + go);
    }

    auto issueKV = [&](int t, int s) {
        const uint32_t st = sKV + s * ASTAGEB;
        const size_t kvrow = (size_t)t * 64;
#pragma unroll
        for (int i = 0; i < 2; i++) {
            int idx = tid + i * 256;
            int row = idx >> 3, ch = idx & 7;
            uint32_t so = (uint32_t)row * ASROWB + ch * 16;
            size_t go = (kvrow + row) * 3072 + ch * 8;
            cp16(st + 0 * AKV_BYTES + so, qkvhi + koff + go);
            cp16(st + 1 * AKV_BYTES + so, qkvlo + koff + go);
            cp16(st + 2 * AKV_BYTES + so, qkvhi + voff + go);
            cp16(st + 3 * AKV_BYTES + so, qkvlo + voff + go);
        }
    };
    issueKV(0, 0);
    CP_COMMIT();

    uint32_t qh[4][4], ql[4][4];
    float o[8][4] = {};
    float mA = -1e30f, mB = -1e30f, lA = 0.f, lB = 0.f;

    const int bN  = ((lane >> 4) << 3) + (lane & 7);
    const int bK8 = ((lane >> 3) & 1) << 3;

    const int NT = SEQ / 64;
    for (int t = 0; t < NT; t++) {
        if (t + 1 < NT) { issueKV(t + 1, (t + 1) & 1); CP_COMMIT(); CP_WAIT(1); }
        else CP_WAIT(0);
        __syncthreads();

        const uint32_t st  = sKV + (t & 1) * ASTAGEB;
        const uint32_t sKh = st;
        const uint32_t sKl = st + AKV_BYTES;
        const uint32_t sVh = st + 2 * AKV_BYTES;
        const uint32_t sVl = st + 3 * AKV_BYTES;

        if (t == 0) {
            const int aRow = wid * 16 + (lane & 15);
            const int aC8  = (lane >> 4) << 3;
#pragma unroll
            for (int ks = 0; ks < 4; ks++) {
                uint32_t off = (uint32_t)aRow * ASROWB + (ks * 16 + aC8) * 2;
                ldm4(qh[ks], sQh + off);
                ldm4(ql[ks], sQl + off);
            }
        }

        float s[8][4] = {};
#pragma unroll
        for (int ks = 0; ks < 4; ks++) {
            uint32_t kbh[4][4], kbl[4][4];
#pragma unroll
            for (int np = 0; np < 4; np++) {
                uint32_t off = (uint32_t)(bN + np * 16) * ASROWB + (ks * 16 + bK8) * 2;
                ldm4(kbh[np], sKh + off);
                ldm4(kbl[np], sKl + off);
            }
#pragma unroll
            for (int nt = 0; nt < 8; nt++) {
                const uint32_t* bh = &kbh[nt >> 1][(nt & 1) * 2];
                const uint32_t* bl = &kbl[nt >> 1][(nt & 1) * 2];
                mma16816(s[nt], qh[ks], bh);
                mma16816(s[nt], qh[ks], bl);
                mma16816(s[nt], ql[ks], bh);
            }
        }

        float rmaxA = -1e30f, rmaxB = -1e30f;
#pragma unroll
        for (int nt = 0; nt < 8; nt++) {
#pragma unroll
            for (int j = 0; j < 4; j++) s[nt][j] *= 0.125f;
            rmaxA = fmaxf(rmaxA, fmaxf(s[nt][0], s[nt][1]));
            rmaxB = fmaxf(rmaxB, fmaxf(s[nt][2], s[nt][3]));
        }
        rmaxA = fmaxf(rmaxA, __shfl_xor_sync(0xffffffffu, rmaxA, 1));
        rmaxA = fmaxf(rmaxA, __shfl_xor_sync(0xffffffffu, rmaxA, 2));
        rmaxB = fmaxf(rmaxB, __shfl_xor_sync(0xffffffffu, rmaxB, 1));
        rmaxB = fmaxf(rmaxB, __shfl_xor_sync(0xffffffffu, rmaxB, 2));

        float mnA = fmaxf(mA, rmaxA), mnB = fmaxf(mB, rmaxB);
        float corrA = __expf(mA - mnA), corrB = __expf(mB - mnB);
        mA = mnA; mB = mnB;

        float rsA = 0.f, rsB = 0.f;
#pragma unroll
        for (int nt = 0; nt < 8; nt++) {
            s[nt][0] = __expf(s[nt][0] - mnA);
            s[nt][1] = __expf(s[nt][1] - mnA);
            s[nt][2] = __expf(s[nt][2] - mnB);
            s[nt][3] = __expf(s[nt][3] - mnB);
            rsA += s[nt][0] + s[nt][1];
            rsB += s[nt][2] + s[nt][3];
        }
        rsA += __shfl_xor_sync(0xffffffffu, rsA, 1);
        rsA += __shfl_xor_sync(0xffffffffu, rsA, 2);
        rsB += __shfl_xor_sync(0xffffffffu, rsB, 1);
        rsB += __shfl_xor_sync(0xffffffffu, rsB, 2);
        lA = lA * corrA + rsA;
        lB = lB * corrB + rsB;
#pragma unroll
        for (int nt = 0; nt < 8; nt++) {
            o[nt][0] *= corrA; o[nt][1] *= corrA;
            o[nt][2] *= corrB; o[nt][3] *= corrB;
        }

#pragma unroll
        for (int t4 = 0; t4 < 4; t4++) {
            uint32_t ph[4], pl[4];
            {
                const float* s0 = s[2 * t4];
                const float* s1 = s[2 * t4 + 1];
                ph[0] = pk_hi2(s0[0], s0[1]);  pl[0] = pk_lo2(s0[0], s0[1]);
                ph[1] = pk_hi2(s0[2], s0[3]);  pl[1] = pk_lo2(s0[2], s0[3]);
                ph[2] = pk_hi2(s1[0], s1[1]);  pl[2] = pk_lo2(s1[0], s1[1]);
                ph[3] = pk_hi2(s1[2], s1[3]);  pl[3] = pk_lo2(s1[2], s1[3]);
            }
#pragma unroll
            for (int np = 0; np < 4; np++) {
                uint32_t vh[4], vl[4];
                uint32_t off = (uint32_t)(t4 * 16 + (lane & 15)) * ASROWB
                             + (np * 16 + ((lane >> 4) << 3)) * 2;
                ldm4t(vh, sVh + off);
                ldm4t(vl, sVl + off);
                mma16816(o[2 * np],     ph, &vh[0]);
                mma16816(o[2 * np],     ph, &vl[0]);
                mma16816(o[2 * np],     pl, &vh[0]);
                mma16816(o[2 * np + 1], ph, &vh[2]);
                mma16816(o[2 * np + 1], ph, &vl[2]);
                mma16816(o[2 * np + 1], pl, &vh[2]);
            }
        }
        __syncthreads();
    }

    const float ivA = 1.f / lA, ivB = 1.f / lB;
    const size_t tokA = row0 + q0 + wid * 16 + (lane >> 2);
    const size_t tokB = tokA + 8;
#pragma unroll
    for (int nt = 0; nt < 8; nt++) {
        const int col = h * 64 + nt * 8 + (lane & 3) * 2;
        float v0 = o[nt][0] * ivA, v1 = o[nt][1] * ivA;
        float v2 = o[nt][2] * ivB, v3 = o[nt][3] * ivB;
        *(uint32_t*)(chi + tokA * D_MODEL + col) = pk_hi2(v0, v1);
        *(uint32_t*)(clo + tokA * D_MODEL + col) = pk_lo2(v0, v1);
        *(uint32_t*)(chi + tokB * D_MODEL + col) = pk_hi2(v2, v3);
        *(uint32_t*)(clo + tokB * D_MODEL + col) = pk_lo2(v2, v3);
    }
}

// ---------------------------------------------------------------------------
// Launch
// ---------------------------------------------------------------------------
extern "C" void kernel_launch(void* const* d_in, const int* in_sizes, int n_in,
                              void* d_out, int out_size)
{
    const float* x      = (const float*)d_in[0];
    const float* w_qkv  = (const float*)d_in[1];
    const float* b_qkv  = (const float*)d_in[2];
    const float* w_proj = (const float*)d_in[3];
    const float* b_proj = (const float*)d_in[4];
    float* out = (float*)d_out;

    __nv_bfloat16 *xhi, *xlo, *qkvhi, *qkvlo, *chi, *clo, *wqhi, *wqlo, *wphi, *wplo;
    cudaGetSymbolAddress((void**)&xhi, g_xhi);
    cudaGetSymbolAddress((void**)&xlo, g_xlo);
    cudaGetSymbolAddress((void**)&qkvhi, g_qkvhi);
    cudaGetSymbolAddress((void**)&qkvlo, g_qkvlo);
    cudaGetSymbolAddress((void**)&chi, g_chi);
    cudaGetSymbolAddress((void**)&clo, g_clo);
    cudaGetSymbolAddress((void**)&wqhi, g_wqhi);
    cudaGetSymbolAddress((void**)&wqlo, g_wqlo);
    cudaGetSymbolAddress((void**)&wphi, g_wphi);
    cudaGetSymbolAddress((void**)&wplo, g_wplo);

    cudaFuncSetAttribute(gemm_mma_bf16x3,
                         cudaFuncAttributeMaxDynamicSharedMemorySize, GEMM_SMEM);
    cudaFuncSetAttribute(attn_mma,
                         cudaFuncAttributeMaxDynamicSharedMemorySize, ATT_SMEM);

    // 1) x -> bf16 hi/lo; weights transpose+split
    {
        int n4 = NTOK * D_MODEL / 4;
        convert_hilo<<<(n4 + 255) / 256, 256>>>((const float4*)x, (uint2*)xhi, (uint2*)xlo, n4);
        dim3 tg(3 * D_MODEL / 32, D_MODEL / 32);
        transpose_hilo<<<tg, dim3(32, 8)>>>(w_qkv, D_MODEL, 3 * D_MODEL, wqhi, wqlo);
        dim3 tp(D_MODEL / 32, D_MODEL / 32);
        transpose_hilo<<<tp, dim3(32, 8)>>>(w_proj, D_MODEL, D_MODEL, wphi, wplo);
    }

    // 2) QKV GEMM -> bf16 hi/lo qkv
    {
        dim3 grid(3 * D_MODEL / 128, NTOK / 128);
        gemm_mma_bf16x3<<<grid, 256, GEMM_SMEM>>>(NTOK, 3 * D_MODEL, D_MODEL,
                                                  xhi, xlo, wqhi, wqlo, b_qkv,
                                                  nullptr, qkvhi, qkvlo, 1);
    }

    // 3) HMMA flash attention -> bf16 hi/lo ctx
    {
        dim3 grid(SEQ / 128, BATCH * HEADS);
        attn_mma<<<grid, 256, ATT_SMEM>>>(qkvhi, qkvlo, chi, clo);
    }

    // 4) Proj GEMM -> fp32 out
    {
        dim3 grid(D_MODEL / 128, NTOK / 128);
        gemm_mma_bf16x3<<<grid, 256, GEMM_SMEM>>>(NTOK, D_MODEL, D_MODEL,
                                                  chi, clo, wphi, wplo, b_proj,
                                                  out, nullptr, nullptr, 0);
    }
}

// round 6
// speedup vs baseline: 2.9953x; 1.0153x over previous
#include <cuda_runtime.h>
#include <cuda_bf16.h>
#include <cstdint>

#define D_MODEL 1024
#define HEADS   16
#define DH      64
#define BATCH   4
#define SEQ     2048
#define NTOK    (BATCH * SEQ)   // 8192

// ---------------- scratch (device globals; no runtime alloc allowed) -------
__device__ __nv_bfloat16 g_xhi[(size_t)NTOK * D_MODEL];
__device__ __nv_bfloat16 g_xlo[(size_t)NTOK * D_MODEL];
__device__ __nv_bfloat16 g_qkvhi[(size_t)NTOK * 3 * D_MODEL]; // [8192,3072]
__device__ __nv_bfloat16 g_qkvlo[(size_t)NTOK * 3 * D_MODEL];
__device__ __nv_bfloat16 g_chi[(size_t)NTOK * D_MODEL];
__device__ __nv_bfloat16 g_clo[(size_t)NTOK * D_MODEL];
__device__ __nv_bfloat16 g_wqhi[(size_t)3 * D_MODEL * D_MODEL]; // Wqkv^T [3072,1024]
__device__ __nv_bfloat16 g_wqlo[(size_t)3 * D_MODEL * D_MODEL];
__device__ __nv_bfloat16 g_wphi[(size_t)D_MODEL * D_MODEL];     // Wproj^T
__device__ __nv_bfloat16 g_wplo[(size_t)D_MODEL * D_MODEL];

// ---------------------------------------------------------------------------
// Helpers (portable ISA only — .target sm_103 without 'a')
// ---------------------------------------------------------------------------
__device__ __forceinline__ uint32_t smem_u32(const void* p) {
    uint32_t a;
    asm("{ .reg .u64 t; cvta.to.shared.u64 t, %1; cvt.u32.u64 %0, t; }"
        : "=r"(a) : "l"(p));
    return a;
}
__device__ __forceinline__ void cp16(uint32_t saddr, const void* gaddr) {
    asm volatile("cp.async.cg.shared.global [%0], [%1], 16;"
        :: "r"(saddr), "l"(gaddr));
}
#define CP_COMMIT() asm volatile("cp.async.commit_group;")
#define CP_WAIT(n)  asm volatile("cp.async.wait_group %0;" :: "n"(n))

__device__ __forceinline__ void ldm4(uint32_t* r, uint32_t a) {
    asm volatile("ldmatrix.sync.aligned.m8n8.x4.shared.b16 {%0,%1,%2,%3}, [%4];"
        : "=r"(r[0]), "=r"(r[1]), "=r"(r[2]), "=r"(r[3]) : "r"(a));
}
__device__ __forceinline__ void ldm4t(uint32_t* r, uint32_t a) {
    asm volatile("ldmatrix.sync.aligned.m8n8.x4.trans.shared.b16 {%0,%1,%2,%3}, [%4];"
        : "=r"(r[0]), "=r"(r[1]), "=r"(r[2]), "=r"(r[3]) : "r"(a));
}
__device__ __forceinline__ void mma16816(float* c, const uint32_t* a, const uint32_t* b) {
    asm volatile(
        "mma.sync.aligned.m16n8k16.row.col.f32.bf16.bf16.f32 "
        "{%0,%1,%2,%3}, {%4,%5,%6,%7}, {%8,%9}, {%0,%1,%2,%3};"
        : "+f"(c[0]), "+f"(c[1]), "+f"(c[2]), "+f"(c[3])
        : "r"(a[0]), "r"(a[1]), "r"(a[2]), "r"(a[3]), "r"(b[0]), "r"(b[1]));
}
__device__ __forceinline__ uint32_t pkbf(__nv_bfloat16 a, __nv_bfloat16 b) {
    __nv_bfloat162 t = __halves2bfloat162(a, b);
    return *reinterpret_cast<uint32_t*>(&t);
}
__device__ __forceinline__ uint32_t pk_hi2(float a, float b) {
    return pkbf(__float2bfloat16(a), __float2bfloat16(b));
}
__device__ __forceinline__ uint32_t pk_lo2(float a, float b) {
    __nv_bfloat16 ha = __float2bfloat16(a), hb = __float2bfloat16(b);
    return pkbf(__float2bfloat16(a - __bfloat162float(ha)),
                __float2bfloat16(b - __bfloat162float(hb)));
}

// swizzled offset in a 32-col bf16 tile (64B rows, 4 chunks)
__device__ __forceinline__ uint32_t gswz(int row, int chunk) {
    return (uint32_t)row * 64 + ((chunk ^ ((row >> 1) & 3)) << 4);
}
// swizzled offset in a 64-col bf16 tile (128B rows, 8 chunks)
__device__ __forceinline__ uint32_t aswz(int row, int chunk) {
    return (uint32_t)row * 128 + ((chunk ^ (row & 7)) << 4);
}

// ---------------------------------------------------------------------------
// Conversion kernels
// ---------------------------------------------------------------------------
__global__ __launch_bounds__(256) void convert_hilo(
    const float4* __restrict__ in, uint2* __restrict__ hi, uint2* __restrict__ lo, int n4)
{
    int i = blockIdx.x * 256 + threadIdx.x;
    if (i >= n4) return;
    float4 v = in[i];
    hi[i] = make_uint2(pk_hi2(v.x, v.y), pk_hi2(v.z, v.w));
    lo[i] = make_uint2(pk_lo2(v.x, v.y), pk_lo2(v.z, v.w));
}

__global__ __launch_bounds__(256) void transpose_hilo(
    const float* __restrict__ W, int K, int N,
    __nv_bfloat16* __restrict__ Thi, __nv_bfloat16* __restrict__ Tlo)
{
    __shared__ float tile[32][33];
    int kb = blockIdx.y * 32, nb = blockIdx.x * 32;
    int tx = threadIdx.x, ty = threadIdx.y;
#pragma unroll
    for (int i = 0; i < 32; i += 8)
        tile[ty + i][tx] = W[(size_t)(kb + ty + i) * N + nb + tx];
    __syncthreads();
#pragma unroll
    for (int i = 0; i < 32; i += 8) {
        int n = nb + ty + i, k = kb + tx;
        float v = tile[tx][ty + i];
        __nv_bfloat16 h = __float2bfloat16(v);
        Thi[(size_t)n * K + k] = h;
        Tlo[(size_t)n * K + k] = __float2bfloat16(v - __bfloat162float(h));
    }
}

// ---------------------------------------------------------------------------
// HMMA bf16x3 GEMM: C = (Ahi+Alo)[M,K] @ (Bhi+Blo)[N,K]^T + bias
// 128x128 CTA tile, K-chunk 32, swizzled 64B rows, 3-stage, 1 sync/iter.
// ---------------------------------------------------------------------------
#define TILEB    8192
#define STAGEB   (4 * TILEB)
#define NSTAGE   3
#define GEMM_SMEM (NSTAGE * STAGEB)  // 98304

__global__ __launch_bounds__(256) void gemm_mma_bf16x3(
    int M, int N, int K,
    const __nv_bfloat16* __restrict__ Ahi, const __nv_bfloat16* __restrict__ Alo,
    const __nv_bfloat16* __restrict__ Bhi, const __nv_bfloat16* __restrict__ Blo,
    const float* __restrict__ bias,
    float* __restrict__ C,
    __nv_bfloat16* __restrict__ Chi, __nv_bfloat16* __restrict__ Clo,
    int hilo_out)
{
    extern __shared__ char smem[];
    const uint32_t sb = smem_u32(smem);

    const int tid = threadIdx.x;
    const int lane = tid & 31;
    const int wid = tid >> 5;
    const int warpM = wid & 3;
    const int warpN = wid >> 2;

    const size_t arow0 = (size_t)blockIdx.y * 128 * K;
    const size_t brow0 = (size_t)blockIdx.x * 128 * K;

    const int ldRow = tid >> 2;
    const int ldCh  = tid & 3;

    float acc[2][8][4] = {};
    const int NCH = K / 32;

    auto issue = [&](int c, int s) {
        const int k0 = c * 32;
        const uint32_t st = sb + s * STAGEB;
#pragma unroll
        for (int p = 0; p < 2; p++) {
            const int row = ldRow + p * 64;
            const uint32_t soff = gswz(row, ldCh);
            const size_t goff = (size_t)row * K + k0 + ldCh * 8;
            cp16(st + 0 * TILEB + soff, Ahi + arow0 + goff);
            cp16(st + 1 * TILEB + soff, Alo + arow0 + goff);
            cp16(st + 2 * TILEB + soff, Bhi + brow0 + goff);
            cp16(st + 3 * TILEB + soff, Blo + brow0 + goff);
        }
    };

    issue(0, 0); CP_COMMIT();
    issue(1, 1); CP_COMMIT();

    for (int c = 0; c < NCH; c++) {
        if (c + 1 < NCH) CP_WAIT(1);
        else CP_WAIT(0);
        __syncthreads();
        if (c + 2 < NCH) { issue(c + 2, (c + 2) % NSTAGE); CP_COMMIT(); }

        const uint32_t st  = sb + (c % NSTAGE) * STAGEB;
        const uint32_t sAh = st;
        const uint32_t sAl = st + TILEB;
        const uint32_t sBh = st + 2 * TILEB;
        const uint32_t sBl = st + 3 * TILEB;

#pragma unroll
        for (int ks = 0; ks < 2; ks++) {
            uint32_t ahi[2][4], alo[2][4];
            const int aRow = warpM * 32 + (lane & 15);
            const int aCh  = ks * 2 + (lane >> 4);
#pragma unroll
            for (int mt = 0; mt < 2; mt++) {
                const uint32_t off = gswz(aRow + mt * 16, aCh);
                ldm4(ahi[mt], sAh + off);
                ldm4(alo[mt], sAl + off);
            }
            uint32_t bhi[4][4], blo[4][4];
            const int bRow = warpN * 64 + ((lane >> 4) << 3) + (lane & 7);
            const int bCh  = ks * 2 + ((lane >> 3) & 1);
#pragma unroll
            for (int ntp = 0; ntp < 4; ntp++) {
                const uint32_t off = gswz(bRow + ntp * 16, bCh);
                ldm4(bhi[ntp], sBh + off);
                ldm4(blo[ntp], sBl + off);
            }
#pragma unroll
            for (int mt = 0; mt < 2; mt++) {
#pragma unroll
                for (int nt = 0; nt < 8; nt++) {
                    const uint32_t* bh = &bhi[nt >> 1][(nt & 1) * 2];
                    const uint32_t* bl = &blo[nt >> 1][(nt & 1) * 2];
                    mma16816(acc[mt][nt], ahi[mt], bh);
                    mma16816(acc[mt][nt], ahi[mt], bl);
                    mma16816(acc[mt][nt], alo[mt], bh);
                }
            }
        }
    }

    const int rBase = blockIdx.y * 128 + warpM * 32 + (lane >> 2);
    const int cBase = blockIdx.x * 128 + warpN * 64 + (lane & 3) * 2;
#pragma unroll
    for (int mt = 0; mt < 2; mt++) {
#pragma unroll
        for (int nt = 0; nt < 8; nt++) {
            const int gc = cBase + nt * 8;
            const float b0 = bias[gc], b1 = bias[gc + 1];
            const int r0 = rBase + mt * 16;
            float v00 = acc[mt][nt][0] + b0, v01 = acc[mt][nt][1] + b1;
            float v10 = acc[mt][nt][2] + b0, v11 = acc[mt][nt][3] + b1;
            if (!hilo_out) {
                *(float2*)(C + (size_t)r0 * N + gc) = make_float2(v00, v01);
                *(float2*)(C + (size_t)(r0 + 8) * N + gc) = make_float2(v10, v11);
            } else {
                *(uint32_t*)(Chi + (size_t)r0 * N + gc) = pk_hi2(v00, v01);
                *(uint32_t*)(Clo + (size_t)r0 * N + gc) = pk_lo2(v00, v01);
                *(uint32_t*)(Chi + (size_t)(r0 + 8) * N + gc) = pk_hi2(v10, v11);
                *(uint32_t*)(Clo + (size_t)(r0 + 8) * N + gc) = pk_lo2(v10, v11);
            }
        }
    }
}

// ---------------------------------------------------------------------------
// HMMA flash attention (bf16x3). 128B swizzled rows -> 98304B smem, 2 CTAs/SM.
// CTA: 128 queries of one (b,h); 8 warps x 16 rows. KV tile 64, dbl-buffered.
// ---------------------------------------------------------------------------
#define AQTILE   16384                    // 128 rows x 128B
#define AKVT     8192                     // 64 rows x 128B
#define ASTAGEB  (4 * AKVT)               // Kh,Kl,Vh,Vl = 32768
#define ATT_SMEM (2 * AQTILE + 2 * ASTAGEB)  // 98304

__global__ __launch_bounds__(256, 2) void attn_mma(
    const __nv_bfloat16* __restrict__ qkvhi,
    const __nv_bfloat16* __restrict__ qkvlo,
    __nv_bfloat16* __restrict__ chi,
    __nv_bfloat16* __restrict__ clo)
{
    extern __shared__ char smem[];
    const uint32_t sb = smem_u32(smem);
    const uint32_t sQh = sb;
    const uint32_t sQl = sb + AQTILE;
    const uint32_t sKV = sb + 2 * AQTILE;

    const int tid = threadIdx.x;
    const int lane = tid & 31;
    const int wid = tid >> 5;

    const int b = blockIdx.y >> 4;
    const int h = blockIdx.y & 15;
    const int q0 = blockIdx.x * 128;
    const size_t row0 = (size_t)b * SEQ;

    const size_t qoff = (row0 + q0) * 3072 + h * 64;
    const size_t koff = row0 * 3072 + 1024 + h * 64;
    const size_t voff = row0 * 3072 + 2048 + h * 64;

    // Q: 128 rows x 8 chunks, hi + lo (swizzled)
#pragma unroll
    for (int i = 0; i < 4; i++) {
        int idx = tid + i * 256;
        int row = idx >> 3, ch = idx & 7;
        uint32_t so = aswz(row, ch);
        size_t go = (size_t)row * 3072 + ch * 8;
        cp16(sQh + so, qkvhi + qoff + go);
        cp16(sQl + so, qkvlo + qoff + go);
    }

    auto issueKV = [&](int t, int s) {
        const uint32_t st = sKV + s * ASTAGEB;
        const size_t kvrow = (size_t)t * 64;
#pragma unroll
        for (int i = 0; i < 2; i++) {
            int idx = tid + i * 256;
            int row = idx >> 3, ch = idx & 7;
            uint32_t so = aswz(row, ch);
            size_t go = (kvrow + row) * 3072 + ch * 8;
            cp16(st + 0 * AKVT + so, qkvhi + koff + go);
            cp16(st + 1 * AKVT + so, qkvlo + koff + go);
            cp16(st + 2 * AKVT + so, qkvhi + voff + go);
            cp16(st + 3 * AKVT + so, qkvlo + voff + go);
        }
    };
    issueKV(0, 0);
    CP_COMMIT();

    float o[8][4] = {};
    float mA = -1e30f, mB = -1e30f, lA = 0.f, lB = 0.f;

    const int NT = SEQ / 64;
    for (int t = 0; t < NT; t++) {
        CP_WAIT(0);
        __syncthreads();
        if (t + 1 < NT) { issueKV(t + 1, (t + 1) & 1); CP_COMMIT(); }

        const uint32_t st  = sKV + (t & 1) * ASTAGEB;
        const uint32_t sKh = st;
        const uint32_t sKl = st + AKVT;
        const uint32_t sVh = st + 2 * AKVT;
        const uint32_t sVl = st + 3 * AKVT;

        // ---- S = Q K^T (bf16x3); Q per-ks, K per-np (low reg pressure)
        float s[8][4] = {};
        const int aRow = wid * 16 + (lane & 15);
        const int bRow0 = ((lane >> 4) << 3) + (lane & 7);
        const int bChSel = (lane >> 3) & 1;
#pragma unroll
        for (int ks = 0; ks < 4; ks++) {
            uint32_t qh4[4], ql4[4];
            {
                uint32_t off = aswz(aRow, ks * 2 + (lane >> 4));
                ldm4(qh4, sQh + off);
                ldm4(ql4, sQl + off);
            }
#pragma unroll
            for (int np = 0; np < 4; np++) {
                uint32_t kh4[4], kl4[4];
                uint32_t off = aswz(bRow0 + np * 16, ks * 2 + bChSel);
                ldm4(kh4, sKh + off);
                ldm4(kl4, sKl + off);
                mma16816(s[2 * np],     qh4, &kh4[0]);
                mma16816(s[2 * np],     qh4, &kl4[0]);
                mma16816(s[2 * np],     ql4, &kh4[0]);
                mma16816(s[2 * np + 1], qh4, &kh4[2]);
                mma16816(s[2 * np + 1], qh4, &kl4[2]);
                mma16816(s[2 * np + 1], ql4, &kh4[2]);
            }
        }

        // ---- online softmax
        float rmaxA = -1e30f, rmaxB = -1e30f;
#pragma unroll
        for (int nt = 0; nt < 8; nt++) {
#pragma unroll
            for (int j = 0; j < 4; j++) s[nt][j] *= 0.125f;
            rmaxA = fmaxf(rmaxA, fmaxf(s[nt][0], s[nt][1]));
            rmaxB = fmaxf(rmaxB, fmaxf(s[nt][2], s[nt][3]));
        }
        rmaxA = fmaxf(rmaxA, __shfl_xor_sync(0xffffffffu, rmaxA, 1));
        rmaxA = fmaxf(rmaxA, __shfl_xor_sync(0xffffffffu, rmaxA, 2));
        rmaxB = fmaxf(rmaxB, __shfl_xor_sync(0xffffffffu, rmaxB, 1));
        rmaxB = fmaxf(rmaxB, __shfl_xor_sync(0xffffffffu, rmaxB, 2));

        float mnA = fmaxf(mA, rmaxA), mnB = fmaxf(mB, rmaxB);
        float corrA = __expf(mA - mnA), corrB = __expf(mB - mnB);
        mA = mnA; mB = mnB;

        float rsA = 0.f, rsB = 0.f;
#pragma unroll
        for (int nt = 0; nt < 8; nt++) {
            s[nt][0] = __expf(s[nt][0] - mnA);
            s[nt][1] = __expf(s[nt][1] - mnA);
            s[nt][2] = __expf(s[nt][2] - mnB);
            s[nt][3] = __expf(s[nt][3] - mnB);
            rsA += s[nt][0] + s[nt][1];
            rsB += s[nt][2] + s[nt][3];
        }
        rsA += __shfl_xor_sync(0xffffffffu, rsA, 1);
        rsA += __shfl_xor_sync(0xffffffffu, rsA, 2);
        rsB += __shfl_xor_sync(0xffffffffu, rsB, 1);
        rsB += __shfl_xor_sync(0xffffffffu, rsB, 2);
        lA = lA * corrA + rsA;
        lB = lB * corrB + rsB;
#pragma unroll
        for (int nt = 0; nt < 8; nt++) {
            o[nt][0] *= corrA; o[nt][1] *= corrA;
            o[nt][2] *= corrB; o[nt][3] *= corrB;
        }

        // ---- O += P V (P hi/lo from registers, V per-np via ldmatrix.trans)
#pragma unroll
        for (int t4 = 0; t4 < 4; t4++) {
            uint32_t ph[4], pl[4];
            {
                const float* s0 = s[2 * t4];
                const float* s1 = s[2 * t4 + 1];
                ph[0] = pk_hi2(s0[0], s0[1]);  pl[0] = pk_lo2(s0[0], s0[1]);
                ph[1] = pk_hi2(s0[2], s0[3]);  pl[1] = pk_lo2(s0[2], s0[3]);
                ph[2] = pk_hi2(s1[0], s1[1]);  pl[2] = pk_lo2(s1[0], s1[1]);
                ph[3] = pk_hi2(s1[2], s1[3]);  pl[3] = pk_lo2(s1[2], s1[3]);
            }
            const int vRow = t4 * 16 + (lane & 15);
#pragma unroll
            for (int np = 0; np < 4; np++) {
                uint32_t vh[4], vl[4];
                uint32_t off = aswz(vRow, np * 2 + (lane >> 4));
                ldm4t(vh, sVh + off);
                ldm4t(vl, sVl + off);
                mma16816(o[2 * np],     ph, &vh[0]);
                mma16816(o[2 * np],     ph, &vl[0]);
                mma16816(o[2 * np],     pl, &vh[0]);
                mma16816(o[2 * np + 1], ph, &vh[2]);
                mma16816(o[2 * np + 1], ph, &vl[2]);
                mma16816(o[2 * np + 1], pl, &vh[2]);
            }
        }
    }

    // ---- epilogue: normalize, split hi/lo, store ctx
    const float ivA = 1.f / lA, ivB = 1.f / lB;
    const size_t tokA = row0 + q0 + wid * 16 + (lane >> 2);
    const size_t tokB = tokA + 8;
#pragma unroll
    for (int nt = 0; nt < 8; nt++) {
        const int col = h * 64 + nt * 8 + (lane & 3) * 2;
        float v0 = o[nt][0] * ivA, v1 = o[nt][1] * ivA;
        float v2 = o[nt][2] * ivB, v3 = o[nt][3] * ivB;
        *(uint32_t*)(chi + tokA * D_MODEL + col) = pk_hi2(v0, v1);
        *(uint32_t*)(clo + tokA * D_MODEL + col) = pk_lo2(v0, v1);
        *(uint32_t*)(chi + tokB * D_MODEL + col) = pk_hi2(v2, v3);
        *(uint32_t*)(clo + tokB * D_MODEL + col) = pk_lo2(v2, v3);
    }
}

// ---------------------------------------------------------------------------
// Launch
// ---------------------------------------------------------------------------
extern "C" void kernel_launch(void* const* d_in, const int* in_sizes, int n_in,
                              void* d_out, int out_size)
{
    const float* x      = (const float*)d_in[0];
    const float* w_qkv  = (const float*)d_in[1];
    const float* b_qkv  = (const float*)d_in[2];
    const float* w_proj = (const float*)d_in[3];
    const float* b_proj = (const float*)d_in[4];
    float* out = (float*)d_out;

    __nv_bfloat16 *xhi, *xlo, *qkvhi, *qkvlo, *chi, *clo, *wqhi, *wqlo, *wphi, *wplo;
    cudaGetSymbolAddress((void**)&xhi, g_xhi);
    cudaGetSymbolAddress((void**)&xlo, g_xlo);
    cudaGetSymbolAddress((void**)&qkvhi, g_qkvhi);
    cudaGetSymbolAddress((void**)&qkvlo, g_qkvlo);
    cudaGetSymbolAddress((void**)&chi, g_chi);
    cudaGetSymbolAddress((void**)&clo, g_clo);
    cudaGetSymbolAddress((void**)&wqhi, g_wqhi);
    cudaGetSymbolAddress((void**)&wqlo, g_wqlo);
    cudaGetSymbolAddress((void**)&wphi, g_wphi);
    cudaGetSymbolAddress((void**)&wplo, g_wplo);

    cudaFuncSetAttribute(gemm_mma_bf16x3,
                         cudaFuncAttributeMaxDynamicSharedMemorySize, GEMM_SMEM);
    cudaFuncSetAttribute(attn_mma,
                         cudaFuncAttributeMaxDynamicSharedMemorySize, ATT_SMEM);

    // 1) x -> bf16 hi/lo; weights transpose+split
    {
        int n4 = NTOK * D_MODEL / 4;
        convert_hilo<<<(n4 + 255) / 256, 256>>>((const float4*)x, (uint2*)xhi, (uint2*)xlo, n4);
        dim3 tg(3 * D_MODEL / 32, D_MODEL / 32);
        transpose_hilo<<<tg, dim3(32, 8)>>>(w_qkv, D_MODEL, 3 * D_MODEL, wqhi, wqlo);
        dim3 tp(D_MODEL / 32, D_MODEL / 32);
        transpose_hilo<<<tp, dim3(32, 8)>>>(w_proj, D_MODEL, D_MODEL, wphi, wplo);
    }

    // 2) QKV GEMM -> bf16 hi/lo qkv
    {
        dim3 grid(3 * D_MODEL / 128, NTOK / 128);
        gemm_mma_bf16x3<<<grid, 256, GEMM_SMEM>>>(NTOK, 3 * D_MODEL, D_MODEL,
                                                  xhi, xlo, wqhi, wqlo, b_qkv,
                                                  nullptr, qkvhi, qkvlo, 1);
    }

    // 3) HMMA flash attention -> bf16 hi/lo ctx
    {
        dim3 grid(SEQ / 128, BATCH * HEADS);
        attn_mma<<<grid, 256, ATT_SMEM>>>(qkvhi, qkvlo, chi, clo);
    }

    // 4) Proj GEMM -> fp32 out
    {
        dim3 grid(D_MODEL / 128, NTOK / 128);
        gemm_mma_bf16x3<<<grid, 256, GEMM_SMEM>>>(NTOK, D_MODEL, D_MODEL,
                                                  chi, clo, wphi, wplo, b_proj,
                                                  out, nullptr, nullptr, 0);
    }
}

// round 7
// speedup vs baseline: 3.2821x; 1.0958x over previous
#include <cuda_runtime.h>
#include <cuda_bf16.h>
#include <cstdint>

#define D_MODEL 1024
#define HEADS   16
#define DH      64
#define BATCH   4
#define SEQ     2048
#define NTOK    (BATCH * SEQ)   // 8192

// ---------------- scratch (device globals; no runtime alloc allowed) -------
__device__ __nv_bfloat16 g_xhi[(size_t)NTOK * D_MODEL];
__device__ __nv_bfloat16 g_xlo[(size_t)NTOK * D_MODEL];
__device__ __nv_bfloat16 g_qkvhi[(size_t)NTOK * 3 * D_MODEL]; // [8192,3072]
__device__ __nv_bfloat16 g_qkvlo[(size_t)NTOK * 3 * D_MODEL];
__device__ __nv_bfloat16 g_chi[(size_t)NTOK * D_MODEL];
__device__ __nv_bfloat16 g_clo[(size_t)NTOK * D_MODEL];
__device__ __nv_bfloat16 g_wqhi[(size_t)3 * D_MODEL * D_MODEL]; // Wqkv^T [3072,1024]
__device__ __nv_bfloat16 g_wqlo[(size_t)3 * D_MODEL * D_MODEL];
__device__ __nv_bfloat16 g_wphi[(size_t)D_MODEL * D_MODEL];     // Wproj^T
__device__ __nv_bfloat16 g_wplo[(size_t)D_MODEL * D_MODEL];

// ---------------------------------------------------------------------------
// Helpers (portable ISA only — .target sm_103 without 'a')
// ---------------------------------------------------------------------------
__device__ __forceinline__ uint32_t smem_u32(const void* p) {
    uint32_t a;
    asm("{ .reg .u64 t; cvta.to.shared.u64 t, %1; cvt.u32.u64 %0, t; }"
        : "=r"(a) : "l"(p));
    return a;
}
__device__ __forceinline__ void cp16(uint32_t saddr, const void* gaddr) {
    asm volatile("cp.async.cg.shared.global [%0], [%1], 16;"
        :: "r"(saddr), "l"(gaddr));
}
#define CP_COMMIT() asm volatile("cp.async.commit_group;")
#define CP_WAIT(n)  asm volatile("cp.async.wait_group %0;" :: "n"(n))

__device__ __forceinline__ void ldm4(uint32_t* r, uint32_t a) {
    asm volatile("ldmatrix.sync.aligned.m8n8.x4.shared.b16 {%0,%1,%2,%3}, [%4];"
        : "=r"(r[0]), "=r"(r[1]), "=r"(r[2]), "=r"(r[3]) : "r"(a));
}
__device__ __forceinline__ void ldm4t(uint32_t* r, uint32_t a) {
    asm volatile("ldmatrix.sync.aligned.m8n8.x4.trans.shared.b16 {%0,%1,%2,%3}, [%4];"
        : "=r"(r[0]), "=r"(r[1]), "=r"(r[2]), "=r"(r[3]) : "r"(a));
}
__device__ __forceinline__ void mma16816(float* c, const uint32_t* a, const uint32_t* b) {
    asm volatile(
        "mma.sync.aligned.m16n8k16.row.col.f32.bf16.bf16.f32 "
        "{%0,%1,%2,%3}, {%4,%5,%6,%7}, {%8,%9}, {%0,%1,%2,%3};"
        : "+f"(c[0]), "+f"(c[1]), "+f"(c[2]), "+f"(c[3])
        : "r"(a[0]), "r"(a[1]), "r"(a[2]), "r"(a[3]), "r"(b[0]), "r"(b[1]));
}
__device__ __forceinline__ uint32_t pkbf(__nv_bfloat16 a, __nv_bfloat16 b) {
    __nv_bfloat162 t = __halves2bfloat162(a, b);
    return *reinterpret_cast<uint32_t*>(&t);
}
__device__ __forceinline__ uint32_t pk_hi2(float a, float b) {
    return pkbf(__float2bfloat16(a), __float2bfloat16(b));
}
__device__ __forceinline__ uint32_t pk_lo2(float a, float b) {
    __nv_bfloat16 ha = __float2bfloat16(a), hb = __float2bfloat16(b);
    return pkbf(__float2bfloat16(a - __bfloat162float(ha)),
                __float2bfloat16(b - __bfloat162float(hb)));
}

// swizzled offset in a 32-col bf16 tile (64B rows, 4 chunks)
__device__ __forceinline__ uint32_t gswz(int row, int chunk) {
    return (uint32_t)row * 64 + ((chunk ^ ((row >> 1) & 3)) << 4);
}
// swizzled offset in a 64-col bf16 tile (128B rows, 8 chunks)
__device__ __forceinline__ uint32_t aswz(int row, int chunk) {
    return (uint32_t)row * 128 + ((chunk ^ (row & 7)) << 4);
}

// ---------------------------------------------------------------------------
// Conversion kernels
// ---------------------------------------------------------------------------
__global__ __launch_bounds__(256) void convert_hilo(
    const float4* __restrict__ in, uint2* __restrict__ hi, uint2* __restrict__ lo, int n4)
{
    int i = blockIdx.x * 256 + threadIdx.x;
    if (i >= n4) return;
    float4 v = in[i];
    hi[i] = make_uint2(pk_hi2(v.x, v.y), pk_hi2(v.z, v.w));
    lo[i] = make_uint2(pk_lo2(v.x, v.y), pk_lo2(v.z, v.w));
}

__global__ __launch_bounds__(256) void transpose_hilo(
    const float* __restrict__ W, int K, int N,
    __nv_bfloat16* __restrict__ Thi, __nv_bfloat16* __restrict__ Tlo)
{
    __shared__ float tile[32][33];
    int kb = blockIdx.y * 32, nb = blockIdx.x * 32;
    int tx = threadIdx.x, ty = threadIdx.y;
#pragma unroll
    for (int i = 0; i < 32; i += 8)
        tile[ty + i][tx] = W[(size_t)(kb + ty + i) * N + nb + tx];
    __syncthreads();
#pragma unroll
    for (int i = 0; i < 32; i += 8) {
        int n = nb + ty + i, k = kb + tx;
        float v = tile[tx][ty + i];
        __nv_bfloat16 h = __float2bfloat16(v);
        Thi[(size_t)n * K + k] = h;
        Tlo[(size_t)n * K + k] = __float2bfloat16(v - __bfloat162float(h));
    }
}

// ---------------------------------------------------------------------------
// HMMA bf16x3 GEMM: C = (Ahi+Alo)[M,K] @ (Bhi+Blo)[N,K]^T + bias
// 128x128 CTA tile, K-chunk 32, swizzled 64B rows, 3-stage, 1 sync/iter.
// __launch_bounds__(256,2): cap regs at 128 so 2 CTAs/SM fit (round-6 lesson).
// ---------------------------------------------------------------------------
#define TILEB    8192
#define STAGEB   (4 * TILEB)
#define NSTAGE   3
#define GEMM_SMEM (NSTAGE * STAGEB)  // 98304

__global__ __launch_bounds__(256, 2) void gemm_mma_bf16x3(
    int M, int N, int K,
    const __nv_bfloat16* __restrict__ Ahi, const __nv_bfloat16* __restrict__ Alo,
    const __nv_bfloat16* __restrict__ Bhi, const __nv_bfloat16* __restrict__ Blo,
    const float* __restrict__ bias,
    float* __restrict__ C,
    __nv_bfloat16* __restrict__ Chi, __nv_bfloat16* __restrict__ Clo,
    int hilo_out)
{
    extern __shared__ char smem[];
    const uint32_t sb = smem_u32(smem);

    const int tid = threadIdx.x;
    const int lane = tid & 31;
    const int wid = tid >> 5;
    const int warpM = wid & 3;
    const int warpN = wid >> 2;

    const size_t arow0 = (size_t)blockIdx.y * 128 * K;
    const size_t brow0 = (size_t)blockIdx.x * 128 * K;

    const int ldRow = tid >> 2;
    const int ldCh  = tid & 3;

    float acc[2][8][4] = {};
    const int NCH = K / 32;

    auto issue = [&](int c, int s) {
        const int k0 = c * 32;
        const uint32_t st = sb + s * STAGEB;
#pragma unroll
        for (int p = 0; p < 2; p++) {
            const int row = ldRow + p * 64;
            const uint32_t soff = gswz(row, ldCh);
            const size_t goff = (size_t)row * K + k0 + ldCh * 8;
            cp16(st + 0 * TILEB + soff, Ahi + arow0 + goff);
            cp16(st + 1 * TILEB + soff, Alo + arow0 + goff);
            cp16(st + 2 * TILEB + soff, Bhi + brow0 + goff);
            cp16(st + 3 * TILEB + soff, Blo + brow0 + goff);
        }
    };

    issue(0, 0); CP_COMMIT();
    issue(1, 1); CP_COMMIT();

    for (int c = 0; c < NCH; c++) {
        if (c + 1 < NCH) CP_WAIT(1);
        else CP_WAIT(0);
        __syncthreads();
        if (c + 2 < NCH) { issue(c + 2, (c + 2) % NSTAGE); CP_COMMIT(); }

        const uint32_t st  = sb + (c % NSTAGE) * STAGEB;
        const uint32_t sAh = st;
        const uint32_t sAl = st + TILEB;
        const uint32_t sBh = st + 2 * TILEB;
        const uint32_t sBl = st + 3 * TILEB;

#pragma unroll
        for (int ks = 0; ks < 2; ks++) {
            uint32_t ahi[2][4], alo[2][4];
            const int aRow = warpM * 32 + (lane & 15);
            const int aCh  = ks * 2 + (lane >> 4);
#pragma unroll
            for (int mt = 0; mt < 2; mt++) {
                const uint32_t off = gswz(aRow + mt * 16, aCh);
                ldm4(ahi[mt], sAh + off);
                ldm4(alo[mt], sAl + off);
            }
            uint32_t bhi[4][4], blo[4][4];
            const int bRow = warpN * 64 + ((lane >> 4) << 3) + (lane & 7);
            const int bCh  = ks * 2 + ((lane >> 3) & 1);
#pragma unroll
            for (int ntp = 0; ntp < 4; ntp++) {
                const uint32_t off = gswz(bRow + ntp * 16, bCh);
                ldm4(bhi[ntp], sBh + off);
                ldm4(blo[ntp], sBl + off);
            }
#pragma unroll
            for (int mt = 0; mt < 2; mt++) {
#pragma unroll
                for (int nt = 0; nt < 8; nt++) {
                    const uint32_t* bh = &bhi[nt >> 1][(nt & 1) * 2];
                    const uint32_t* bl = &blo[nt >> 1][(nt & 1) * 2];
                    mma16816(acc[mt][nt], ahi[mt], bh);
                    mma16816(acc[mt][nt], ahi[mt], bl);
                    mma16816(acc[mt][nt], alo[mt], bh);
                }
            }
        }
    }

    const int rBase = blockIdx.y * 128 + warpM * 32 + (lane >> 2);
    const int cBase = blockIdx.x * 128 + warpN * 64 + (lane & 3) * 2;
#pragma unroll
    for (int mt = 0; mt < 2; mt++) {
#pragma unroll
        for (int nt = 0; nt < 8; nt++) {
            const int gc = cBase + nt * 8;
            const float b0 = bias[gc], b1 = bias[gc + 1];
            const int r0 = rBase + mt * 16;
            float v00 = acc[mt][nt][0] + b0, v01 = acc[mt][nt][1] + b1;
            float v10 = acc[mt][nt][2] + b0, v11 = acc[mt][nt][3] + b1;
            if (!hilo_out) {
                *(float2*)(C + (size_t)r0 * N + gc) = make_float2(v00, v01);
                *(float2*)(C + (size_t)(r0 + 8) * N + gc) = make_float2(v10, v11);
            } else {
                *(uint32_t*)(Chi + (size_t)r0 * N + gc) = pk_hi2(v00, v01);
                *(uint32_t*)(Clo + (size_t)r0 * N + gc) = pk_lo2(v00, v01);
                *(uint32_t*)(Chi + (size_t)(r0 + 8) * N + gc) = pk_hi2(v10, v11);
                *(uint32_t*)(Clo + (size_t)(r0 + 8) * N + gc) = pk_lo2(v10, v11);
            }
        }
    }
}

// ---------------------------------------------------------------------------
// HMMA flash attention (bf16x3). 128B swizzled rows -> 98304B smem, 2 CTAs/SM.
// CTA: 128 queries of one (b,h); 8 warps x 16 rows. KV tile 64, dbl-buffered.
// (unchanged from round 6 — measured win)
// ---------------------------------------------------------------------------
#define AQTILE   16384
#define AKVT     8192
#define ASTAGEB  (4 * AKVT)
#define ATT_SMEM (2 * AQTILE + 2 * ASTAGEB)  // 98304

__global__ __launch_bounds__(256, 2) void attn_mma(
    const __nv_bfloat16* __restrict__ qkvhi,
    const __nv_bfloat16* __restrict__ qkvlo,
    __nv_bfloat16* __restrict__ chi,
    __nv_bfloat16* __restrict__ clo)
{
    extern __shared__ char smem[];
    const uint32_t sb = smem_u32(smem);
    const uint32_t sQh = sb;
    const uint32_t sQl = sb + AQTILE;
    const uint32_t sKV = sb + 2 * AQTILE;

    const int tid = threadIdx.x;
    const int lane = tid & 31;
    const int wid = tid >> 5;

    const int b = blockIdx.y >> 4;
    const int h = blockIdx.y & 15;
    const int q0 = blockIdx.x * 128;
    const size_t row0 = (size_t)b * SEQ;

    const size_t qoff = (row0 + q0) * 3072 + h * 64;
    const size_t koff = row0 * 3072 + 1024 + h * 64;
    const size_t voff = row0 * 3072 + 2048 + h * 64;

#pragma unroll
    for (int i = 0; i < 4; i++) {
        int idx = tid + i * 256;
        int row = idx >> 3, ch = idx & 7;
        uint32_t so = aswz(row, ch);
        size_t go = (size_t)row * 3072 + ch * 8;
        cp16(sQh + so, qkvhi + qoff + go);
        cp16(sQl + so, qkvlo + qoff + go);
    }

    auto issueKV = [&](int t, int s) {
        const uint32_t st = sKV + s * ASTAGEB;
        const size_t kvrow = (size_t)t * 64;
#pragma unroll
        for (int i = 0; i < 2; i++) {
            int idx = tid + i * 256;
            int row = idx >> 3, ch = idx & 7;
            uint32_t so = aswz(row, ch);
            size_t go = (kvrow + row) * 3072 + ch * 8;
            cp16(st + 0 * AKVT + so, qkvhi + koff + go);
            cp16(st + 1 * AKVT + so, qkvlo + koff + go);
            cp16(st + 2 * AKVT + so, qkvhi + voff + go);
            cp16(st + 3 * AKVT + so, qkvlo + voff + go);
        }
    };
    issueKV(0, 0);
    CP_COMMIT();

    float o[8][4] = {};
    float mA = -1e30f, mB = -1e30f, lA = 0.f, lB = 0.f;

    const int NT = SEQ / 64;
    for (int t = 0; t < NT; t++) {
        CP_WAIT(0);
        __syncthreads();
        if (t + 1 < NT) { issueKV(t + 1, (t + 1) & 1); CP_COMMIT(); }

        const uint32_t st  = sKV + (t & 1) * ASTAGEB;
        const uint32_t sKh = st;
        const uint32_t sKl = st + AKVT;
        const uint32_t sVh = st + 2 * AKVT;
        const uint32_t sVl = st + 3 * AKVT;

        float s[8][4] = {};
        const int aRow = wid * 16 + (lane & 15);
        const int bRow0 = ((lane >> 4) << 3) + (lane & 7);
        const int bChSel = (lane >> 3) & 1;
#pragma unroll
        for (int ks = 0; ks < 4; ks++) {
            uint32_t qh4[4], ql4[4];
            {
                uint32_t off = aswz(aRow, ks * 2 + (lane >> 4));
                ldm4(qh4, sQh + off);
                ldm4(ql4, sQl + off);
            }
#pragma unroll
            for (int np = 0; np < 4; np++) {
                uint32_t kh4[4], kl4[4];
                uint32_t off = aswz(bRow0 + np * 16, ks * 2 + bChSel);
                ldm4(kh4, sKh + off);
                ldm4(kl4, sKl + off);
                mma16816(s[2 * np],     qh4, &kh4[0]);
                mma16816(s[2 * np],     qh4, &kl4[0]);
                mma16816(s[2 * np],     ql4, &kh4[0]);
                mma16816(s[2 * np + 1], qh4, &kh4[2]);
                mma16816(s[2 * np + 1], qh4, &kl4[2]);
                mma16816(s[2 * np + 1], ql4, &kh4[2]);
            }
        }

        float rmaxA = -1e30f, rmaxB = -1e30f;
#pragma unroll
        for (int nt = 0; nt < 8; nt++) {
#pragma unroll
            for (int j = 0; j < 4; j++) s[nt][j] *= 0.125f;
            rmaxA = fmaxf(rmaxA, fmaxf(s[nt][0], s[nt][1]));
            rmaxB = fmaxf(rmaxB, fmaxf(s[nt][2], s[nt][3]));
        }
        rmaxA = fmaxf(rmaxA, __shfl_xor_sync(0xffffffffu, rmaxA, 1));
        rmaxA = fmaxf(rmaxA, __shfl_xor_sync(0xffffffffu, rmaxA, 2));
        rmaxB = fmaxf(rmaxB, __shfl_xor_sync(0xffffffffu, rmaxB, 1));
        rmaxB = fmaxf(rmaxB, __shfl_xor_sync(0xffffffffu, rmaxB, 2));

        float mnA = fmaxf(mA, rmaxA), mnB = fmaxf(mB, rmaxB);
        float corrA = __expf(mA - mnA), corrB = __expf(mB - mnB);
        mA = mnA; mB = mnB;

        float rsA = 0.f, rsB = 0.f;
#pragma unroll
        for (int nt = 0; nt < 8; nt++) {
            s[nt][0] = __expf(s[nt][0] - mnA);
            s[nt][1] = __expf(s[nt][1] - mnA);
            s[nt][2] = __expf(s[nt][2] - mnB);
            s[nt][3] = __expf(s[nt][3] - mnB);
            rsA += s[nt][0] + s[nt][1];
            rsB += s[nt][2] + s[nt][3];
        }
        rsA += __shfl_xor_sync(0xffffffffu, rsA, 1);
        rsA += __shfl_xor_sync(0xffffffffu, rsA, 2);
        rsB += __shfl_xor_sync(0xffffffffu, rsB, 1);
        rsB += __shfl_xor_sync(0xffffffffu, rsB, 2);
        lA = lA * corrA + rsA;
        lB = lB * corrB + rsB;
#pragma unroll
        for (int nt = 0; nt < 8; nt++) {
            o[nt][0] *= corrA; o[nt][1] *= corrA;
            o[nt][2] *= corrB; o[nt][3] *= corrB;
        }

#pragma unroll
        for (int t4 = 0; t4 < 4; t4++) {
            uint32_t ph[4], pl[4];
            {
                const float* s0 = s[2 * t4];
                const float* s1 = s[2 * t4 + 1];
                ph[0] = pk_hi2(s0[0], s0[1]);  pl[0] = pk_lo2(s0[0], s0[1]);
                ph[1] = pk_hi2(s0[2], s0[3]);  pl[1] = pk_lo2(s0[2], s0[3]);
                ph[2] = pk_hi2(s1[0], s1[1]);  pl[2] = pk_lo2(s1[0], s1[1]);
                ph[3] = pk_hi2(s1[2], s1[3]);  pl[3] = pk_lo2(s1[2], s1[3]);
            }
            const int vRow = t4 * 16 + (lane & 15);
#pragma unroll
            for (int np = 0; np < 4; np++) {
                uint32_t vh[4], vl[4];
                uint32_t off = aswz(vRow, np * 2 + (lane >> 4));
                ldm4t(vh, sVh + off);
                ldm4t(vl, sVl + off);
                mma16816(o[2 * np],     ph, &vh[0]);
                mma16816(o[2 * np],     ph, &vl[0]);
                mma16816(o[2 * np],     pl, &vh[0]);
                mma16816(o[2 * np + 1], ph, &vh[2]);
                mma16816(o[2 * np + 1], ph, &vl[2]);
                mma16816(o[2 * np + 1], pl, &vh[2]);
            }
        }
    }

    const float ivA = 1.f / lA, ivB = 1.f / lB;
    const size_t tokA = row0 + q0 + wid * 16 + (lane >> 2);
    const size_t tokB = tokA + 8;
#pragma unroll
    for (int nt = 0; nt < 8; nt++) {
        const int col = h * 64 + nt * 8 + (lane & 3) * 2;
        float v0 = o[nt][0] * ivA, v1 = o[nt][1] * ivA;
        float v2 = o[nt][2] * ivB, v3 = o[nt][3] * ivB;
        *(uint32_t*)(chi + tokA * D_MODEL + col) = pk_hi2(v0, v1);
        *(uint32_t*)(clo + tokA * D_MODEL + col) = pk_lo2(v0, v1);
        *(uint32_t*)(chi + tokB * D_MODEL + col) = pk_hi2(v2, v3);
        *(uint32_t*)(clo + tokB * D_MODEL + col) = pk_lo2(v2, v3);
    }
}

// ---------------------------------------------------------------------------
// Launch
// ---------------------------------------------------------------------------
extern "C" void kernel_launch(void* const* d_in, const int* in_sizes, int n_in,
                              void* d_out, int out_size)
{
    const float* x      = (const float*)d_in[0];
    const float* w_qkv  = (const float*)d_in[1];
    const float* b_qkv  = (const float*)d_in[2];
    const float* w_proj = (const float*)d_in[3];
    const float* b_proj = (const float*)d_in[4];
    float* out = (float*)d_out;

    __nv_bfloat16 *xhi, *xlo, *qkvhi, *qkvlo, *chi, *clo, *wqhi, *wqlo, *wphi, *wplo;
    cudaGetSymbolAddress((void**)&xhi, g_xhi);
    cudaGetSymbolAddress((void**)&xlo, g_xlo);
    cudaGetSymbolAddress((void**)&qkvhi, g_qkvhi);
    cudaGetSymbolAddress((void**)&qkvlo, g_qkvlo);
    cudaGetSymbolAddress((void**)&chi, g_chi);
    cudaGetSymbolAddress((void**)&clo, g_clo);
    cudaGetSymbolAddress((void**)&wqhi, g_wqhi);
    cudaGetSymbolAddress((void**)&wqlo, g_wqlo);
    cudaGetSymbolAddress((void**)&wphi, g_wphi);
    cudaGetSymbolAddress((void**)&wplo, g_wplo);

    cudaFuncSetAttribute(gemm_mma_bf16x3,
                         cudaFuncAttributeMaxDynamicSharedMemorySize, GEMM_SMEM);
    cudaFuncSetAttribute(attn_mma,
                         cudaFuncAttributeMaxDynamicSharedMemorySize, ATT_SMEM);

    // 1) x -> bf16 hi/lo; weights transpose+split
    {
        int n4 = NTOK * D_MODEL / 4;
        convert_hilo<<<(n4 + 255) / 256, 256>>>((const float4*)x, (uint2*)xhi, (uint2*)xlo, n4);
        dim3 tg(3 * D_MODEL / 32, D_MODEL / 32);
        transpose_hilo<<<tg, dim3(32, 8)>>>(w_qkv, D_MODEL, 3 * D_MODEL, wqhi, wqlo);
        dim3 tp(D_MODEL / 32, D_MODEL / 32);
        transpose_hilo<<<tp, dim3(32, 8)>>>(w_proj, D_MODEL, D_MODEL, wphi, wplo);
    }

    // 2) QKV GEMM -> bf16 hi/lo qkv
    {
        dim3 grid(3 * D_MODEL / 128, NTOK / 128);
        gemm_mma_bf16x3<<<grid, 256, GEMM_SMEM>>>(NTOK, 3 * D_MODEL, D_MODEL,
                                                  xhi, xlo, wqhi, wqlo, b_qkv,
                                                  nullptr, qkvhi, qkvlo, 1);
    }

    // 3) HMMA flash attention -> bf16 hi/lo ctx
    {
        dim3 grid(SEQ / 128, BATCH * HEADS);
        attn_mma<<<grid, 256, ATT_SMEM>>>(qkvhi, qkvlo, chi, clo);
    }

    // 4) Proj GEMM -> fp32 out
    {
        dim3 grid(D_MODEL / 128, NTOK / 128);
        gemm_mma_bf16x3<<<grid, 256, GEMM_SMEM>>>(NTOK, D_MODEL, D_MODEL,
                                                  chi, clo, wphi, wplo, b_proj,
                                                  out, nullptr, nullptr, 0);
    }
}